// round 4
// baseline (speedup 1.0000x reference)
#include <cuda_runtime.h>
#include <cstdint>

// Problem dims (fixed by setup_inputs)
#define BATCH 4
#define NG 64
#define NP 4096
#define NH 8
#define PCHUNK 256   // p points per block
#define RPT 16       // rows per pair-iteration
#define PAIRS 4      // 8 warps = 4 warp-pairs, one g each

struct __align__(16) Smem {
    float4 W2v[32 * 64];            // [k4][c] = {W2[4k4..4k4+3][c]}   32 KB
    float4 W3v[16 * 8];             // A3 = g2-scaled W3, [c4][h]       2 KB
    float4 sp[PCHUNK];              // scene points {x,y,z,0}           4 KB
    float  hb[PAIRS][RPT * 128];    // normalized h1 tiles             32 KB
    float  h2r[PAIRS][RPT * 68];    // raw v (pre-LN2), pitch 68       17 KB
    int2   pstat[PAIRS][RPT][2];    // fixed-point LN2 partials         1 KB
    float  obuf[PAIRS][8 * 36];     // staged outputs                   4.5 KB
};

__device__ __forceinline__ uint64_t ffma2(uint64_t a, uint64_t b, uint64_t c) {
    uint64_t d;
    asm("fma.rn.f32x2 %0, %1, %2, %3;" : "=l"(d) : "l"(a), "l"(b), "l"(c));
    return d;
}
__device__ __forceinline__ float lo32(uint64_t v) { return __uint_as_float((unsigned)(v & 0xffffffffu)); }
__device__ __forceinline__ float hi32(uint64_t v) { return __uint_as_float((unsigned)(v >> 32)); }
__device__ __forceinline__ int redux_s32(int v) {
    int r;
    asm("redux.sync.add.s32 %0, %1, 0xffffffff;" : "=r"(r) : "r"(v));
    return r;
}

// Fixed-point scales for LN stats
#define SC1B 262144.f      // 2^18, stage B sum
#define SC2B 16384.f       // 2^14, stage B sumsq
#define SC1C 1048576.f     // 2^20, stage C sum
#define SC2C 262144.f      // 2^18, stage C sumsq

__global__ void __launch_bounds__(256, 2)
gab_kernel(const float* __restrict__ scene,   // (B, NP, 3)
           const float* __restrict__ poses,   // (B, NG, 7)
           const float* __restrict__ W1, const float* __restrict__ b1,
           const float* __restrict__ g1, const float* __restrict__ be1,
           const float* __restrict__ W2, const float* __restrict__ b2,
           const float* __restrict__ g2, const float* __restrict__ be2,
           const float* __restrict__ W3, const float* __restrict__ b3,
           const float* __restrict__ bscale,
           float* __restrict__ out)            // (B, NH, NG, NP)
{
    extern __shared__ __align__(16) char smraw[];
    Smem& sm = *reinterpret_cast<Smem*>(smraw);

    const int tid = threadIdx.x;
    const int b = blockIdx.z;
    const int gbase = blockIdx.y * 4;
    const int p0 = blockIdx.x * PCHUNK;

    // ---- Stage shared: W2 (float4 over K), A3 = g2*W3, scene chunk ----
    for (int idx = tid; idx < 32 * 64; idx += 256) {
        int k4 = idx >> 6, c = idx & 63;
        sm.W2v[idx] = make_float4(W2[(4 * k4 + 0) * 64 + c], W2[(4 * k4 + 1) * 64 + c],
                                  W2[(4 * k4 + 2) * 64 + c], W2[(4 * k4 + 3) * 64 + c]);
    }
    if (tid < 128) {
        int c4 = tid >> 3, h = tid & 7;
        sm.W3v[tid] = make_float4(g2[4 * c4 + 0] * W3[(4 * c4 + 0) * 8 + h],
                                  g2[4 * c4 + 1] * W3[(4 * c4 + 1) * 8 + h],
                                  g2[4 * c4 + 2] * W3[(4 * c4 + 2) * 8 + h],
                                  g2[4 * c4 + 3] * W3[(4 * c4 + 3) * 8 + h]);
    }
    if (tid < PCHUNK) {
        const float* spp = scene + ((size_t)b * NP + p0 + tid) * 3;
        sm.sp[tid] = make_float4(spp[0], spp[1], spp[2], 0.f);
    }
    __syncthreads();

    const int wid = tid >> 5, lane = tid & 31;
    const int pair = wid >> 1, wsub = wid & 1;
    const int g = gbase + pair;
    const int hD = lane & 7, r0D = lane >> 3;
    const int c_own = wsub * 32 + lane;

    // ---- Register-cached small weights ----
    // Stage B: lane owns j = 4*lane + q (q=0..3)
    const float4 w1f0 = __ldg((const float4*)W1 + lane);
    const float4 w1f1 = __ldg((const float4*)W1 + 32 + lane);
    const float4 w1f2 = __ldg((const float4*)W1 + 64 + lane);
    const float4 w1f3 = __ldg((const float4*)W1 + 96 + lane);
    const float4 b1q  = __ldg((const float4*)b1 + lane);
    const float4 g1q  = __ldg((const float4*)g1 + lane);
    const float4 be1q = __ldg((const float4*)be1 + lane);
    const float b2r = __ldg(b2 + c_own);
    // LN2-fold constants per output head hD: K1 = be2@W3, K2 = g2@W3
    float K1 = 0.f, K2 = 0.f;
    #pragma unroll 8
    for (int c = 0; c < 64; ++c) {
        float w = __ldg(W3 + c * 8 + hD);
        K1 = fmaf(__ldg(be2 + c), w, K1);
        K2 = fmaf(__ldg(g2 + c), w, K2);
    }
    const float b3r = __ldg(b3 + hD), bsr = __ldg(bscale + hD);
    const float C0 = (K1 + b3r) * bsr;

    // Per-pair pose -> rotation (both warps compute redundantly)
    const float* pp = poses + ((size_t)(b * NG + g)) * 7;
    float tx = pp[0], ty = pp[1], tz = pp[2];
    float qx = pp[3], qy = pp[4], qz = pp[5], qw = pp[6];
    float inv = 1.f / (sqrtf(qx * qx + qy * qy + qz * qz + qw * qw) + 1e-8f);
    qx *= inv; qy *= inv; qz *= inv; qw *= inv;
    float xx = qx * qx, yy = qy * qy, zz = qz * qz;
    float xy = qx * qy, xz = qx * qz, yz = qy * qz;
    float wx = qw * qx, wy = qw * qy, wz = qw * qz;
    float R00 = 1.f - 2.f * (yy + zz), R01 = 2.f * (xy - wz), R02 = 2.f * (xz + wy);
    float R10 = 2.f * (xy + wz), R11 = 1.f - 2.f * (xx + zz), R12 = 2.f * (yz - wx);
    float R20 = 2.f * (xz - wy), R21 = 2.f * (yz + wx), R22 = 1.f - 2.f * (xx + yy);

    float* hbp = sm.hb[pair];
    float* h2p = sm.h2r[pair];
    float* ob  = sm.obuf[pair];
    const ulonglong2* w2u = reinterpret_cast<const ulonglong2*>(sm.W2v);
    const ulonglong2* w3u = reinterpret_cast<const ulonglong2*>(sm.W3v);

    const size_t outbase = (((size_t)b * NH) * NG + g) * NP + p0;

    #define BARP() asm volatile("bar.sync %0, 64;" :: "r"(pair + 1) : "memory")

    for (int it = 0; it < PCHUNK / RPT; ++it) {
        // ---- Stage B: 8 rows per warp -> normalized h1 tile ----
        #pragma unroll 2
        for (int rr = 0; rr < 8; ++rr) {
            const int rloc = wsub * 8 + rr;
            float4 P = sm.sp[it * RPT + rloc];
            float rx = P.x - tx, ry = P.y - ty, rz = P.z - tz;
            float lx = R00 * rx + R10 * ry + R20 * rz;
            float ly = R01 * rx + R11 * ry + R21 * rz;
            float lz = R02 * rx + R12 * ry + R22 * rz;
            float dd = sqrtf(lx * lx + ly * ly + lz * lz);
            float a0 = fmaxf(fmaf(lx, w1f0.x, fmaf(ly, w1f1.x, fmaf(lz, w1f2.x, fmaf(dd, w1f3.x, b1q.x)))), 0.f);
            float a1 = fmaxf(fmaf(lx, w1f0.y, fmaf(ly, w1f1.y, fmaf(lz, w1f2.y, fmaf(dd, w1f3.y, b1q.y)))), 0.f);
            float a2 = fmaxf(fmaf(lx, w1f0.z, fmaf(ly, w1f1.z, fmaf(lz, w1f2.z, fmaf(dd, w1f3.z, b1q.z)))), 0.f);
            float a3 = fmaxf(fmaf(lx, w1f0.w, fmaf(ly, w1f1.w, fmaf(lz, w1f2.w, fmaf(dd, w1f3.w, b1q.w)))), 0.f);
            float s  = (a0 + a1) + (a2 + a3);
            float s2 = fmaf(a0, a0, fmaf(a1, a1, fmaf(a2, a2, a3 * a3)));
            int is = redux_s32(__float2int_rn(s * SC1B));
            int iq = redux_s32(__float2int_rn(s2 * SC2B));
            float mu  = (float)is * (1.f / (SC1B * 128.f));
            float ex2 = (float)iq * (1.f / (SC2B * 128.f));
            float rs = rsqrtf(fmaxf(ex2 - mu * mu, 0.f) + 1e-5f);
            float4 hv;
            hv.x = fmaf((a0 - mu) * rs, g1q.x, be1q.x);
            hv.y = fmaf((a1 - mu) * rs, g1q.y, be1q.y);
            hv.z = fmaf((a2 - mu) * rs, g1q.z, be1q.z);
            hv.w = fmaf((a3 - mu) * rs, g1q.w, be1q.w);
            reinterpret_cast<float4*>(hbp + rloc * 128)[lane] = hv;
        }
        BARP();

        // ---- Stage C: h1 @ W2, 16 rows x 1 col per lane ----
        uint64_t acc[RPT];
        #pragma unroll
        for (int r = 0; r < RPT; ++r) acc[r] = 0ull;
        const ulonglong2* hb4 = reinterpret_cast<const ulonglong2*>(hbp);
        #pragma unroll 2
        for (int k4 = 0; k4 < 32; ++k4) {
            ulonglong2 wv = w2u[k4 * 64 + c_own];
            #pragma unroll
            for (int r = 0; r < RPT; ++r) {
                ulonglong2 hp = hb4[r * 32 + k4];   // broadcast, 4 K-values
                acc[r] = ffma2(hp.x, wv.x, acc[r]);
                acc[r] = ffma2(hp.y, wv.y, acc[r]);
            }
        }
        // epilogue: bias+relu, write RAW v, fixed-point stats
        #pragma unroll 2
        for (int r = 0; r < RPT; ++r) {
            float v = lo32(acc[r]) + hi32(acc[r]) + b2r;
            v = fmaxf(v, 0.f);
            h2p[r * 68 + c_own] = v;
            int is = redux_s32(__float2int_rn(v * SC1C));
            int iq = redux_s32(__float2int_rn(v * v * SC2C));
            if (lane == 0) sm.pstat[pair][r][wsub] = make_int2(is, iq);
        }
        BARP();

        // ---- Stage D: LN2 folded into h2r @ A3 ----
        const int rA = wsub * 8 + r0D, rB = rA + 4;
        int4 stA = *reinterpret_cast<const int4*>(&sm.pstat[pair][rA][0]);
        int4 stB = *reinterpret_cast<const int4*>(&sm.pstat[pair][rB][0]);
        float sA  = (float)(stA.x + stA.z) * (1.f / (SC1C * 64.f));
        float qA  = (float)(stA.y + stA.w) * (1.f / (SC2C * 64.f));
        float rsA = rsqrtf(fmaxf(qA - sA * sA, 0.f) + 1e-5f);
        float sB  = (float)(stB.x + stB.z) * (1.f / (SC1C * 64.f));
        float qB  = (float)(stB.y + stB.w) * (1.f / (SC2C * 64.f));
        float rsB = rsqrtf(fmaxf(qB - sB * sB, 0.f) + 1e-5f);

        uint64_t a0 = 0ull, a1 = 0ull;
        const ulonglong2* h0  = reinterpret_cast<const ulonglong2*>(h2p + rA * 68);
        const ulonglong2* h1p = reinterpret_cast<const ulonglong2*>(h2p + rB * 68);
        #pragma unroll
        for (int c4 = 0; c4 < 16; ++c4) {
            ulonglong2 wp = w3u[c4 * 8 + hD];
            ulonglong2 ha = h0[c4];
            ulonglong2 hc = h1p[c4];
            a0 = ffma2(ha.x, wp.x, a0);
            a0 = ffma2(ha.y, wp.y, a0);
            a1 = ffma2(hc.x, wp.x, a1);
            a1 = ffma2(hc.y, wp.y, a1);
        }
        float S0 = lo32(a0) + hi32(a0);
        float S1 = lo32(a1) + hi32(a1);
        float m1A = rsA * bsr, m1B = rsB * bsr;
        float oA = fmaf(S0, m1A, fmaf(-sA * m1A, K2, C0));
        float oB = fmaf(S1, m1B, fmaf(-sB * m1B, K2, C0));
        const int w = it & 1;
        ob[hD * 36 + w * 16 + rA] = oA;
        ob[hD * 36 + w * 16 + rB] = oB;

        if (w == 1) {
            BARP();
            const int pw = (it - 1) * RPT;
            #pragma unroll
            for (int hh = 0; hh < 4; ++hh) {
                int h = wsub * 4 + hh;
                out[outbase + (size_t)h * (NG * NP) + pw + lane] = ob[h * 36 + lane];
            }
            BARP();
        }
    }
    #undef BARP
}

extern "C" void kernel_launch(void* const* d_in, const int* in_sizes, int n_in,
                              void* d_out, int out_size) {
    // metadata order: grasp_tokens, scene_points, grasp_poses, W1, b1, g1, beta1,
    //                 W2, b2, g2, beta2, W3, b3, bias_scale
    const float* scene  = (const float*)d_in[1];
    const float* poses  = (const float*)d_in[2];
    const float* W1     = (const float*)d_in[3];
    const float* b1     = (const float*)d_in[4];
    const float* g1     = (const float*)d_in[5];
    const float* be1    = (const float*)d_in[6];
    const float* W2     = (const float*)d_in[7];
    const float* b2     = (const float*)d_in[8];
    const float* g2     = (const float*)d_in[9];
    const float* be2    = (const float*)d_in[10];
    const float* W3     = (const float*)d_in[11];
    const float* b3     = (const float*)d_in[12];
    const float* bscale = (const float*)d_in[13];
    float* out = (float*)d_out;

    cudaFuncSetAttribute(gab_kernel, cudaFuncAttributeMaxDynamicSharedMemorySize,
                         (int)sizeof(Smem));
    dim3 grid(NP / PCHUNK, NG / 4, BATCH);
    gab_kernel<<<grid, 256, sizeof(Smem)>>>(scene, poses, W1, b1, g1, be1,
                                            W2, b2, g2, be2, W3, b3, bscale, out);
}

// round 5
// speedup vs baseline: 1.7729x; 1.7729x over previous
#include <cuda_runtime.h>
#include <cstdint>

// Problem dims (fixed by setup_inputs)
#define BATCH 4
#define NG 64
#define NP 4096
#define NH 8
#define PCHUNK 256
#define TILE 16
#define HPITCH 132   // fp32 words; 132 % 32 == 4 -> <=2-way bank groups
#define VPITCH 68    // fp32 words; 68 % 32 == 4

// Fixed-point scales for LN1 stats (validated round 4)
#define SC1B 262144.f      // 2^18
#define SC2B 16384.f       // 2^14

struct __align__(16) Smem {
    uint4  Bp[8][8][32];          // [kb][nb][lane] = {bhi0,bhi1,blo0,blo1}  32 KB
    float4 W3v[16 * 8];           // A3 = g2*W3, [c4][h]                      2 KB
    float4 sp[PCHUNK];            // scene points                             4 KB
    float  b2s[64];               //                                          256 B
    float  h[8][TILE * HPITCH];   // per-warp h1 fp32                        67.6 KB
    float  v[8][TILE * VPITCH];   // per-warp raw v fp32                     34.8 KB
    float2 pstat[8][TILE];        // (mu, rs) per row                         1 KB
    float  obuf[8][8 * 36];       // staged outputs                           9.2 KB
};

__device__ __forceinline__ uint64_t ffma2(uint64_t a, uint64_t b, uint64_t c) {
    uint64_t d;
    asm("fma.rn.f32x2 %0, %1, %2, %3;" : "=l"(d) : "l"(a), "l"(b), "l"(c));
    return d;
}
__device__ __forceinline__ float lo32(uint64_t v) { return __uint_as_float((unsigned)(v & 0xffffffffu)); }
__device__ __forceinline__ float hi32(uint64_t v) { return __uint_as_float((unsigned)(v >> 32)); }
__device__ __forceinline__ int redux_s32(int v) {
    int r;
    asm("redux.sync.add.s32 %0, %1, 0xffffffff;" : "=r"(r) : "r"(v));
    return r;
}
// Pack (x0 -> low half, x1 -> high half) as bf16x2; produce hi and residual lo.
__device__ __forceinline__ void split2(float x0, float x1, unsigned& hi, unsigned& lo) {
    asm("cvt.rn.bf16x2.f32 %0, %1, %2;" : "=r"(hi) : "f"(x1), "f"(x0));
    float h0 = __uint_as_float(hi << 16);
    float h1 = __uint_as_float(hi & 0xffff0000u);
    asm("cvt.rn.bf16x2.f32 %0, %1, %2;" : "=r"(lo) : "f"(x1 - h1), "f"(x0 - h0));
}
__device__ __forceinline__ void mma16816(float d[4], const unsigned a[4],
                                         unsigned b0, unsigned b1) {
    asm volatile(
        "mma.sync.aligned.m16n8k16.row.col.f32.bf16.bf16.f32 "
        "{%0,%1,%2,%3},{%4,%5,%6,%7},{%8,%9},{%0,%1,%2,%3};"
        : "+f"(d[0]), "+f"(d[1]), "+f"(d[2]), "+f"(d[3])
        : "r"(a[0]), "r"(a[1]), "r"(a[2]), "r"(a[3]), "r"(b0), "r"(b1));
}

__global__ void __launch_bounds__(256, 1)
gab_kernel(const float* __restrict__ scene,   // (B, NP, 3)
           const float* __restrict__ poses,   // (B, NG, 7)
           const float* __restrict__ W1, const float* __restrict__ b1,
           const float* __restrict__ g1, const float* __restrict__ be1,
           const float* __restrict__ W2, const float* __restrict__ b2,
           const float* __restrict__ g2, const float* __restrict__ be2,
           const float* __restrict__ W3, const float* __restrict__ b3,
           const float* __restrict__ bscale,
           float* __restrict__ out)            // (B, NH, NG, NP)
{
    extern __shared__ __align__(16) char smraw[];
    Smem& sm = *reinterpret_cast<Smem*>(smraw);

    const int tid = threadIdx.x;
    const int b = blockIdx.z;
    const int gbase = blockIdx.y * 8;
    const int p0 = blockIdx.x * PCHUNK;

    // ---- Build fragment-ordered split-bf16 W2 pack; stage W3v/b2/scene ----
    for (int idx = tid; idx < 8 * 8 * 32; idx += 256) {
        int kb = idx >> 8, rem = idx & 255;
        int nb = rem >> 5, ln = rem & 31;
        int t = ln & 3, c = ln >> 2;
        int n = nb * 8 + c;
        int k0 = kb * 16 + 2 * t;
        float w00 = W2[(k0 + 0) * 64 + n], w01 = W2[(k0 + 1) * 64 + n];
        float w10 = W2[(k0 + 8) * 64 + n], w11 = W2[(k0 + 9) * 64 + n];
        unsigned hi0, lo0, hi1, lo1;
        split2(w00, w01, hi0, lo0);
        split2(w10, w11, hi1, lo1);
        sm.Bp[kb][nb][ln] = make_uint4(hi0, hi1, lo0, lo1);
    }
    if (tid < 128) {
        int c4 = tid >> 3, hh = tid & 7;
        sm.W3v[tid] = make_float4(g2[4 * c4 + 0] * W3[(4 * c4 + 0) * 8 + hh],
                                  g2[4 * c4 + 1] * W3[(4 * c4 + 1) * 8 + hh],
                                  g2[4 * c4 + 2] * W3[(4 * c4 + 2) * 8 + hh],
                                  g2[4 * c4 + 3] * W3[(4 * c4 + 3) * 8 + hh]);
    }
    if (tid < 64) sm.b2s[tid] = b2[tid];
    if (tid < PCHUNK) {
        const float* spp = scene + ((size_t)b * NP + p0 + tid) * 3;
        sm.sp[tid] = make_float4(spp[0], spp[1], spp[2], 0.f);
    }
    __syncthreads();

    const int wid = tid >> 5, lane = tid & 31;
    const int g = gbase + wid;
    const int t = lane & 3, gg = lane >> 2;      // mma fragment coords
    const int hD = lane & 7, r0D = lane >> 3;    // stage D coords

    // ---- Register-cached stage-B weights (lane owns h cols 4*lane..4*lane+3) ----
    const float4 w1f0 = __ldg((const float4*)W1 + lane);
    const float4 w1f1 = __ldg((const float4*)W1 + 32 + lane);
    const float4 w1f2 = __ldg((const float4*)W1 + 64 + lane);
    const float4 w1f3 = __ldg((const float4*)W1 + 96 + lane);
    const float4 b1q  = __ldg((const float4*)b1 + lane);
    const float4 g1q  = __ldg((const float4*)g1 + lane);
    const float4 be1q = __ldg((const float4*)be1 + lane);

    // LN2-fold constants per head hD: K1 = be2@W3, K2 = g2@W3
    float K1 = 0.f, K2 = 0.f;
    #pragma unroll 8
    for (int c = 0; c < 64; ++c) {
        float w = __ldg(W3 + c * 8 + hD);
        K1 = fmaf(__ldg(be2 + c), w, K1);
        K2 = fmaf(__ldg(g2 + c), w, K2);
    }
    const float b3r = __ldg(b3 + hD), bsr = __ldg(bscale + hD);
    const float C0 = (K1 + b3r) * bsr;

    // Per-warp pose -> rotation
    const float* pp = poses + ((size_t)(b * NG + g)) * 7;
    float tx = pp[0], ty = pp[1], tz = pp[2];
    float qx = pp[3], qy = pp[4], qz = pp[5], qw = pp[6];
    float inv = 1.f / (sqrtf(qx * qx + qy * qy + qz * qz + qw * qw) + 1e-8f);
    qx *= inv; qy *= inv; qz *= inv; qw *= inv;
    float xx = qx * qx, yy = qy * qy, zz = qz * qz;
    float xy = qx * qy, xz = qx * qz, yz = qy * qz;
    float wx = qw * qx, wy = qw * qy, wz = qw * qz;
    float R00 = 1.f - 2.f * (yy + zz), R01 = 2.f * (xy - wz), R02 = 2.f * (xz + wy);
    float R10 = 2.f * (xy + wz), R11 = 1.f - 2.f * (xx + zz), R12 = 2.f * (yz - wx);
    float R20 = 2.f * (xz - wy), R21 = 2.f * (yz + wx), R22 = 1.f - 2.f * (xx + yy);

    float* hw = sm.h[wid];
    float* vw = sm.v[wid];
    float* ob = sm.obuf[wid];
    const ulonglong2* w3u = reinterpret_cast<const ulonglong2*>(sm.W3v);
    const size_t outbase = (((size_t)b * NH) * NG + g) * NP + p0;

    for (int it = 0; it < PCHUNK / TILE; ++it) {
        // ---- Stage B: 16 rows -> normalized h1 (fp32 in shared) ----
        #pragma unroll 2
        for (int r = 0; r < TILE; ++r) {
            float4 P = sm.sp[it * TILE + r];
            float rx = P.x - tx, ry = P.y - ty, rz = P.z - tz;
            float lx = R00 * rx + R10 * ry + R20 * rz;
            float ly = R01 * rx + R11 * ry + R21 * rz;
            float lz = R02 * rx + R12 * ry + R22 * rz;
            float dd = sqrtf(lx * lx + ly * ly + lz * lz);
            float a0 = fmaxf(fmaf(lx, w1f0.x, fmaf(ly, w1f1.x, fmaf(lz, w1f2.x, fmaf(dd, w1f3.x, b1q.x)))), 0.f);
            float a1 = fmaxf(fmaf(lx, w1f0.y, fmaf(ly, w1f1.y, fmaf(lz, w1f2.y, fmaf(dd, w1f3.y, b1q.y)))), 0.f);
            float a2 = fmaxf(fmaf(lx, w1f0.z, fmaf(ly, w1f1.z, fmaf(lz, w1f2.z, fmaf(dd, w1f3.z, b1q.z)))), 0.f);
            float a3 = fmaxf(fmaf(lx, w1f0.w, fmaf(ly, w1f1.w, fmaf(lz, w1f2.w, fmaf(dd, w1f3.w, b1q.w)))), 0.f);
            float s  = (a0 + a1) + (a2 + a3);
            float s2 = fmaf(a0, a0, fmaf(a1, a1, fmaf(a2, a2, a3 * a3)));
            int is = redux_s32(__float2int_rn(s * SC1B));
            int iq = redux_s32(__float2int_rn(s2 * SC2B));
            float mu  = (float)is * (1.f / (SC1B * 128.f));
            float ex2 = (float)iq * (1.f / (SC2B * 128.f));
            float rs = rsqrtf(fmaxf(ex2 - mu * mu, 0.f) + 1e-5f);
            float4 hv;
            hv.x = fmaf((a0 - mu) * rs, g1q.x, be1q.x);
            hv.y = fmaf((a1 - mu) * rs, g1q.y, be1q.y);
            hv.z = fmaf((a2 - mu) * rs, g1q.z, be1q.z);
            hv.w = fmaf((a3 - mu) * rs, g1q.w, be1q.w);
            *reinterpret_cast<float4*>(hw + r * HPITCH + 4 * lane) = hv;
        }
        __syncwarp();

        // ---- Stage C: 16x64x128 via bf16 3-term mma ----
        float d[8][4];
        #pragma unroll
        for (int nb = 0; nb < 8; ++nb) { d[nb][0] = d[nb][1] = d[nb][2] = d[nb][3] = 0.f; }

        #pragma unroll 2
        for (int kb = 0; kb < 8; ++kb) {
            const float* hr0 = hw + gg * HPITCH + kb * 16 + 2 * t;
            const float* hr1 = hw + (gg + 8) * HPITCH + kb * 16 + 2 * t;
            float2 x0 = *reinterpret_cast<const float2*>(hr0);
            float2 x1 = *reinterpret_cast<const float2*>(hr1);
            float2 x2 = *reinterpret_cast<const float2*>(hr0 + 8);
            float2 x3 = *reinterpret_cast<const float2*>(hr1 + 8);
            unsigned ahi[4], alo[4];
            split2(x0.x, x0.y, ahi[0], alo[0]);
            split2(x1.x, x1.y, ahi[1], alo[1]);
            split2(x2.x, x2.y, ahi[2], alo[2]);
            split2(x3.x, x3.y, ahi[3], alo[3]);
            #pragma unroll
            for (int nb = 0; nb < 8; ++nb) {
                uint4 bp = sm.Bp[kb][nb][lane];
                mma16816(d[nb], ahi, bp.x, bp.y);   // Ahi * Bhi
                mma16816(d[nb], alo, bp.x, bp.y);   // Alo * Bhi
                mma16816(d[nb], ahi, bp.z, bp.w);   // Ahi * Blo
            }
        }

        // ---- Epilogue: bias+relu, store raw v, LN2 stats ----
        float sg = 0.f, qg = 0.f, sh = 0.f, qh = 0.f;
        #pragma unroll
        for (int nb = 0; nb < 8; ++nb) {
            float2 bb = *reinterpret_cast<const float2*>(sm.b2s + nb * 8 + 2 * t);
            float v00 = fmaxf(d[nb][0] + bb.x, 0.f);
            float v01 = fmaxf(d[nb][1] + bb.y, 0.f);
            float v10 = fmaxf(d[nb][2] + bb.x, 0.f);
            float v11 = fmaxf(d[nb][3] + bb.y, 0.f);
            *reinterpret_cast<float2*>(vw + gg * VPITCH + nb * 8 + 2 * t) = make_float2(v00, v01);
            *reinterpret_cast<float2*>(vw + (gg + 8) * VPITCH + nb * 8 + 2 * t) = make_float2(v10, v11);
            sg += v00 + v01; qg = fmaf(v00, v00, fmaf(v01, v01, qg));
            sh += v10 + v11; qh = fmaf(v10, v10, fmaf(v11, v11, qh));
        }
        #pragma unroll
        for (int o = 1; o <= 2; o <<= 1) {
            sg += __shfl_xor_sync(0xffffffffu, sg, o);
            qg += __shfl_xor_sync(0xffffffffu, qg, o);
            sh += __shfl_xor_sync(0xffffffffu, sh, o);
            qh += __shfl_xor_sync(0xffffffffu, qh, o);
        }
        if (t == 0) {
            float mug = sg * (1.f / 64.f);
            float rsg = rsqrtf(fmaxf(qg * (1.f / 64.f) - mug * mug, 0.f) + 1e-5f);
            float muh = sh * (1.f / 64.f);
            float rsh = rsqrtf(fmaxf(qh * (1.f / 64.f) - muh * muh, 0.f) + 1e-5f);
            sm.pstat[wid][gg]     = make_float2(mug, rsg);
            sm.pstat[wid][gg + 8] = make_float2(muh, rsh);
        }
        __syncwarp();

        // ---- Stage D: folded-LN2 h2 @ A3; lane = (hD, rows r0D+4i) ----
        uint64_t acc[4] = {0ull, 0ull, 0ull, 0ull};
        #pragma unroll 4
        for (int c4 = 0; c4 < 16; ++c4) {
            ulonglong2 wp = w3u[c4 * 8 + hD];
            #pragma unroll
            for (int i = 0; i < 4; ++i) {
                ulonglong2 hv = *reinterpret_cast<const ulonglong2*>(vw + (r0D + 4 * i) * VPITCH + 4 * c4);
                acc[i] = ffma2(hv.x, wp.x, acc[i]);
                acc[i] = ffma2(hv.y, wp.y, acc[i]);
            }
        }
        const int w = it & 1;
        #pragma unroll
        for (int i = 0; i < 4; ++i) {
            int r = r0D + 4 * i;
            float2 st = sm.pstat[wid][r];
            float S = lo32(acc[i]) + hi32(acc[i]);
            float m1 = st.y * bsr;
            float o = fmaf(S, m1, fmaf(-st.x * m1, K2, C0));
            ob[hD * 36 + w * 16 + r] = o;
        }

        if (w == 1) {
            __syncwarp();
            const int pw = (it - 1) * TILE;
            #pragma unroll
            for (int hh = 0; hh < 8; ++hh)
                out[outbase + (size_t)hh * (NG * NP) + pw + lane] = ob[hh * 36 + lane];
        }
        __syncwarp();   // protect v/h/obuf reuse across iterations
    }
}

extern "C" void kernel_launch(void* const* d_in, const int* in_sizes, int n_in,
                              void* d_out, int out_size) {
    // metadata order: grasp_tokens, scene_points, grasp_poses, W1, b1, g1, beta1,
    //                 W2, b2, g2, beta2, W3, b3, bias_scale
    const float* scene  = (const float*)d_in[1];
    const float* poses  = (const float*)d_in[2];
    const float* W1     = (const float*)d_in[3];
    const float* b1     = (const float*)d_in[4];
    const float* g1     = (const float*)d_in[5];
    const float* be1    = (const float*)d_in[6];
    const float* W2     = (const float*)d_in[7];
    const float* b2     = (const float*)d_in[8];
    const float* g2     = (const float*)d_in[9];
    const float* be2    = (const float*)d_in[10];
    const float* W3     = (const float*)d_in[11];
    const float* b3     = (const float*)d_in[12];
    const float* bscale = (const float*)d_in[13];
    float* out = (float*)d_out;

    cudaFuncSetAttribute(gab_kernel, cudaFuncAttributeMaxDynamicSharedMemorySize,
                         (int)sizeof(Smem));
    dim3 grid(NP / PCHUNK, NG / 8, BATCH);
    gab_kernel<<<grid, 256, sizeof(Smem)>>>(scene, poses, W1, b1, g1, be1,
                                            W2, b2, g2, be2, W3, b3, bscale, out);
}

// round 6
// speedup vs baseline: 2.5577x; 1.4427x over previous
#include <cuda_runtime.h>
#include <cstdint>

// Problem dims (fixed by setup_inputs)
#define BATCH 4
#define NG 64
#define NH 8
#define NP 4096
#define PCHUNK 256
#define TILE 16
#define HPITCH 132   // fp32 words; 132 % 32 == 4

// Fixed-point scales for LN1 stats (validated)
#define SC1B 262144.f      // 2^18
#define SC2B 16384.f       // 2^14

struct __align__(16) Smem {
    uint4  Bp[8][8][32];          // W2 split-bf16 fragments            32 KB
    float4 sp[PCHUNK];            // scene points                        4 KB
    float  b2s[64];               //                                    256 B
    float  h[8][TILE * HPITCH];   // per-warp h1 fp32                 67.6 KB
    float  obuf[8][8 * 36];       // staged outputs                    9.2 KB
};                                 // total ~113.9 KB -> 2 blocks/SM

__device__ __forceinline__ int redux_s32(int v) {
    int r;
    asm("redux.sync.add.s32 %0, %1, 0xffffffff;" : "=r"(r) : "r"(v));
    return r;
}
// Pack (x0 -> low half, x1 -> high half) as bf16x2; produce hi and residual lo.
__device__ __forceinline__ void split2(float x0, float x1, unsigned& hi, unsigned& lo) {
    asm("cvt.rn.bf16x2.f32 %0, %1, %2;" : "=r"(hi) : "f"(x1), "f"(x0));
    float h0 = __uint_as_float(hi << 16);
    float h1 = __uint_as_float(hi & 0xffff0000u);
    asm("cvt.rn.bf16x2.f32 %0, %1, %2;" : "=r"(lo) : "f"(x1 - h1), "f"(x0 - h0));
}
__device__ __forceinline__ void mma16816(float d[4], const unsigned a[4],
                                         unsigned b0, unsigned b1) {
    asm volatile(
        "mma.sync.aligned.m16n8k16.row.col.f32.bf16.bf16.f32 "
        "{%0,%1,%2,%3},{%4,%5,%6,%7},{%8,%9},{%0,%1,%2,%3};"
        : "+f"(d[0]), "+f"(d[1]), "+f"(d[2]), "+f"(d[3])
        : "r"(a[0]), "r"(a[1]), "r"(a[2]), "r"(a[3]), "r"(b0), "r"(b1));
}

__global__ void __launch_bounds__(256, 2)
gab_kernel(const float* __restrict__ scene,   // (B, NP, 3)
           const float* __restrict__ poses,   // (B, NG, 7)
           const float* __restrict__ W1, const float* __restrict__ b1,
           const float* __restrict__ g1, const float* __restrict__ be1,
           const float* __restrict__ W2, const float* __restrict__ b2,
           const float* __restrict__ g2, const float* __restrict__ be2,
           const float* __restrict__ W3, const float* __restrict__ b3,
           const float* __restrict__ bscale,
           float* __restrict__ out)            // (B, NH, NG, NP)
{
    extern __shared__ __align__(16) char smraw[];
    Smem& sm = *reinterpret_cast<Smem*>(smraw);

    const int tid = threadIdx.x;
    const int b = blockIdx.z;
    const int gbase = blockIdx.y * 8;
    const int p0 = blockIdx.x * PCHUNK;

    // ---- Build fragment-ordered split-bf16 W2 pack; stage b2/scene ----
    for (int idx = tid; idx < 8 * 8 * 32; idx += 256) {
        int kb = idx >> 8, rem = idx & 255;
        int nb = rem >> 5, ln = rem & 31;
        int tt = ln & 3, c = ln >> 2;
        int n = nb * 8 + c;
        int k0 = kb * 16 + 2 * tt;
        float w00 = W2[(k0 + 0) * 64 + n], w01 = W2[(k0 + 1) * 64 + n];
        float w10 = W2[(k0 + 8) * 64 + n], w11 = W2[(k0 + 9) * 64 + n];
        unsigned hi0, lo0, hi1, lo1;
        split2(w00, w01, hi0, lo0);
        split2(w10, w11, hi1, lo1);
        sm.Bp[kb][nb][ln] = make_uint4(hi0, hi1, lo0, lo1);
    }
    if (tid < 64) sm.b2s[tid] = b2[tid];
    if (tid < PCHUNK) {
        const float* spp = scene + ((size_t)b * NP + p0 + tid) * 3;
        sm.sp[tid] = make_float4(spp[0], spp[1], spp[2], 0.f);
    }
    __syncthreads();

    const int wid = tid >> 5, lane = tid & 31;
    const int g = gbase + wid;
    const int t = lane & 3, gg = lane >> 2;   // mma fragment coords

    // ---- Register-cached stage-B weights (lane owns h cols 4*lane..4*lane+3) ----
    const float4 w1f0 = __ldg((const float4*)W1 + lane);
    const float4 w1f1 = __ldg((const float4*)W1 + 32 + lane);
    const float4 w1f2 = __ldg((const float4*)W1 + 64 + lane);
    const float4 w1f3 = __ldg((const float4*)W1 + 96 + lane);
    const float4 b1q  = __ldg((const float4*)b1 + lane);
    const float4 g1q  = __ldg((const float4*)g1 + lane);
    const float4 be1q = __ldg((const float4*)be1 + lane);

    // ---- Stage-D B-fragments: A3 = g2 (*) W3, split bf16, n = gg ----
    unsigned bDh0[4], bDh1[4], bDl0[4], bDl1[4];
    #pragma unroll
    for (int kb2 = 0; kb2 < 4; ++kb2) {
        int k0 = kb2 * 16 + 2 * t;
        float a0 = __ldg(g2 + k0 + 0) * __ldg(W3 + (k0 + 0) * 8 + gg);
        float a1 = __ldg(g2 + k0 + 1) * __ldg(W3 + (k0 + 1) * 8 + gg);
        float a2 = __ldg(g2 + k0 + 8) * __ldg(W3 + (k0 + 8) * 8 + gg);
        float a3 = __ldg(g2 + k0 + 9) * __ldg(W3 + (k0 + 9) * 8 + gg);
        split2(a0, a1, bDh0[kb2], bDl0[kb2]);
        split2(a2, a3, bDh1[kb2], bDl1[kb2]);
    }

    // ---- Per-head fold constants for heads h0 = 2t, h1 = 2t+1 ----
    float K2a = 0.f, K2b = 0.f, K1a = 0.f, K1b = 0.f;
    #pragma unroll 8
    for (int c = 0; c < 64; ++c) {
        float2 w = *reinterpret_cast<const float2*>(W3 + c * 8 + 2 * t);
        float gc = __ldg(g2 + c), bc = __ldg(be2 + c);
        K2a = fmaf(gc, w.x, K2a); K2b = fmaf(gc, w.y, K2b);
        K1a = fmaf(bc, w.x, K1a); K1b = fmaf(bc, w.y, K1b);
    }
    const float bsa = __ldg(bscale + 2 * t), bsb = __ldg(bscale + 2 * t + 1);
    const float C0a = (K1a + __ldg(b3 + 2 * t)) * bsa;
    const float C0b = (K1b + __ldg(b3 + 2 * t + 1)) * bsb;

    // Per-warp pose -> rotation
    const float* pp = poses + ((size_t)(b * NG + g)) * 7;
    float tx = pp[0], ty = pp[1], tz = pp[2];
    float qx = pp[3], qy = pp[4], qz = pp[5], qw = pp[6];
    float inv = 1.f / (sqrtf(qx * qx + qy * qy + qz * qz + qw * qw) + 1e-8f);
    qx *= inv; qy *= inv; qz *= inv; qw *= inv;
    float xx = qx * qx, yy = qy * qy, zz = qz * qz;
    float xy = qx * qy, xz = qx * qz, yz = qy * qz;
    float wx = qw * qx, wy = qw * qy, wz = qw * qz;
    float R00 = 1.f - 2.f * (yy + zz), R01 = 2.f * (xy - wz), R02 = 2.f * (xz + wy);
    float R10 = 2.f * (xy + wz), R11 = 1.f - 2.f * (xx + zz), R12 = 2.f * (yz - wx);
    float R20 = 2.f * (xz - wy), R21 = 2.f * (yz + wx), R22 = 1.f - 2.f * (xx + yy);

    float* hw = sm.h[wid];
    float* ob = sm.obuf[wid];
    const size_t outbase = (((size_t)b * NH) * NG + g) * NP + p0;

    for (int it = 0; it < PCHUNK / TILE; ++it) {
        // ---- Stage B: 16 rows -> normalized h1 (fp32 in shared) ----
        #pragma unroll 2
        for (int r = 0; r < TILE; ++r) {
            float4 P = sm.sp[it * TILE + r];
            float rx = P.x - tx, ry = P.y - ty, rz = P.z - tz;
            float lx = R00 * rx + R10 * ry + R20 * rz;
            float ly = R01 * rx + R11 * ry + R21 * rz;
            float lz = R02 * rx + R12 * ry + R22 * rz;
            float dd = sqrtf(lx * lx + ly * ly + lz * lz);
            float a0 = fmaxf(fmaf(lx, w1f0.x, fmaf(ly, w1f1.x, fmaf(lz, w1f2.x, fmaf(dd, w1f3.x, b1q.x)))), 0.f);
            float a1 = fmaxf(fmaf(lx, w1f0.y, fmaf(ly, w1f1.y, fmaf(lz, w1f2.y, fmaf(dd, w1f3.y, b1q.y)))), 0.f);
            float a2 = fmaxf(fmaf(lx, w1f0.z, fmaf(ly, w1f1.z, fmaf(lz, w1f2.z, fmaf(dd, w1f3.z, b1q.z)))), 0.f);
            float a3 = fmaxf(fmaf(lx, w1f0.w, fmaf(ly, w1f1.w, fmaf(lz, w1f2.w, fmaf(dd, w1f3.w, b1q.w)))), 0.f);
            float s  = (a0 + a1) + (a2 + a3);
            float s2 = fmaf(a0, a0, fmaf(a1, a1, fmaf(a2, a2, a3 * a3)));
            int is = redux_s32(__float2int_rn(s * SC1B));
            int iq = redux_s32(__float2int_rn(s2 * SC2B));
            float mu  = (float)is * (1.f / (SC1B * 128.f));
            float ex2 = (float)iq * (1.f / (SC2B * 128.f));
            float rs = rsqrtf(fmaxf(ex2 - mu * mu, 0.f) + 1e-5f);
            float4 hv;
            hv.x = fmaf((a0 - mu) * rs, g1q.x, be1q.x);
            hv.y = fmaf((a1 - mu) * rs, g1q.y, be1q.y);
            hv.z = fmaf((a2 - mu) * rs, g1q.z, be1q.z);
            hv.w = fmaf((a3 - mu) * rs, g1q.w, be1q.w);
            *reinterpret_cast<float4*>(hw + r * HPITCH + 4 * lane) = hv;
        }
        __syncwarp();

        // ---- Stage C: 16x64x128 via bf16 3-term mma ----
        float d[8][4];
        #pragma unroll
        for (int nb = 0; nb < 8; ++nb) { d[nb][0] = d[nb][1] = d[nb][2] = d[nb][3] = 0.f; }

        #pragma unroll 2
        for (int kb = 0; kb < 8; ++kb) {
            const float* hr0 = hw + gg * HPITCH + kb * 16 + 2 * t;
            const float* hr1 = hw + (gg + 8) * HPITCH + kb * 16 + 2 * t;
            float2 x0 = *reinterpret_cast<const float2*>(hr0);
            float2 x1 = *reinterpret_cast<const float2*>(hr1);
            float2 x2 = *reinterpret_cast<const float2*>(hr0 + 8);
            float2 x3 = *reinterpret_cast<const float2*>(hr1 + 8);
            unsigned ahi[4], alo[4];
            split2(x0.x, x0.y, ahi[0], alo[0]);
            split2(x1.x, x1.y, ahi[1], alo[1]);
            split2(x2.x, x2.y, ahi[2], alo[2]);
            split2(x3.x, x3.y, ahi[3], alo[3]);
            #pragma unroll
            for (int nb = 0; nb < 8; ++nb) {
                uint4 bp = sm.Bp[kb][nb][lane];
                mma16816(d[nb], ahi, bp.x, bp.y);   // Ahi * Bhi
                mma16816(d[nb], alo, bp.x, bp.y);   // Alo * Bhi
                mma16816(d[nb], ahi, bp.z, bp.w);   // Ahi * Blo
            }
        }

        // ---- Fused epilogue + Stage D: v = relu(d+b2) -> split -> mma vs A3 ----
        float ddd[4] = {0.f, 0.f, 0.f, 0.f};
        float sg = 0.f, qg = 0.f, sh = 0.f, qh = 0.f;
        #pragma unroll
        for (int kb2 = 0; kb2 < 4; ++kb2) {
            const int nb0 = 2 * kb2, nb1 = 2 * kb2 + 1;
            float2 bb0 = *reinterpret_cast<const float2*>(sm.b2s + nb0 * 8 + 2 * t);
            float2 bb1 = *reinterpret_cast<const float2*>(sm.b2s + nb1 * 8 + 2 * t);
            float v00 = fmaxf(d[nb0][0] + bb0.x, 0.f), v01 = fmaxf(d[nb0][1] + bb0.y, 0.f);
            float v10 = fmaxf(d[nb0][2] + bb0.x, 0.f), v11 = fmaxf(d[nb0][3] + bb0.y, 0.f);
            float v20 = fmaxf(d[nb1][0] + bb1.x, 0.f), v21 = fmaxf(d[nb1][1] + bb1.y, 0.f);
            float v30 = fmaxf(d[nb1][2] + bb1.x, 0.f), v31 = fmaxf(d[nb1][3] + bb1.y, 0.f);
            sg += (v00 + v01) + (v20 + v21);
            qg = fmaf(v00, v00, fmaf(v01, v01, fmaf(v20, v20, fmaf(v21, v21, qg))));
            sh += (v10 + v11) + (v30 + v31);
            qh = fmaf(v10, v10, fmaf(v11, v11, fmaf(v30, v30, fmaf(v31, v31, qh))));
            unsigned ahi[4], alo[4];
            split2(v00, v01, ahi[0], alo[0]);
            split2(v10, v11, ahi[1], alo[1]);
            split2(v20, v21, ahi[2], alo[2]);
            split2(v30, v31, ahi[3], alo[3]);
            mma16816(ddd, ahi, bDh0[kb2], bDh1[kb2]);   // vhi * A3hi
            mma16816(ddd, alo, bDh0[kb2], bDh1[kb2]);   // vlo * A3hi
            mma16816(ddd, ahi, bDl0[kb2], bDl1[kb2]);   // vhi * A3lo
        }
        #pragma unroll
        for (int o = 1; o <= 2; o <<= 1) {
            sg += __shfl_xor_sync(0xffffffffu, sg, o);
            qg += __shfl_xor_sync(0xffffffffu, qg, o);
            sh += __shfl_xor_sync(0xffffffffu, sh, o);
            qh += __shfl_xor_sync(0xffffffffu, qh, o);
        }
        float muA = sg * (1.f / 64.f);
        float rsA = rsqrtf(fmaxf(qg * (1.f / 64.f) - muA * muA, 0.f) + 1e-5f);
        float muB = sh * (1.f / 64.f);
        float rsB = rsqrtf(fmaxf(qh * (1.f / 64.f) - muB * muB, 0.f) + 1e-5f);

        // fold LN2: out = (S - mu*K2)*rs*bs + C0
        const int w = it & 1;
        {
            float m1 = rsA * bsa, m2 = rsA * bsb;
            ob[(2 * t + 0) * 36 + w * 16 + gg] = fmaf(ddd[0], m1, fmaf(-muA * m1, K2a, C0a));
            ob[(2 * t + 1) * 36 + w * 16 + gg] = fmaf(ddd[1], m2, fmaf(-muA * m2, K2b, C0b));
            float m3 = rsB * bsa, m4 = rsB * bsb;
            ob[(2 * t + 0) * 36 + w * 16 + gg + 8] = fmaf(ddd[2], m3, fmaf(-muB * m3, K2a, C0a));
            ob[(2 * t + 1) * 36 + w * 16 + gg + 8] = fmaf(ddd[3], m4, fmaf(-muB * m4, K2b, C0b));
        }

        if (w == 1) {
            __syncwarp();
            const int pw = (it - 1) * TILE;
            #pragma unroll
            for (int hh = 0; hh < 8; ++hh)
                out[outbase + (size_t)hh * (NG * NP) + pw + lane] = ob[hh * 36 + lane];
        }
        __syncwarp();   // protect h/obuf reuse across iterations
    }
}

extern "C" void kernel_launch(void* const* d_in, const int* in_sizes, int n_in,
                              void* d_out, int out_size) {
    // metadata order: grasp_tokens, scene_points, grasp_poses, W1, b1, g1, beta1,
    //                 W2, b2, g2, beta2, W3, b3, bias_scale
    const float* scene  = (const float*)d_in[1];
    const float* poses  = (const float*)d_in[2];
    const float* W1     = (const float*)d_in[3];
    const float* b1     = (const float*)d_in[4];
    const float* g1     = (const float*)d_in[5];
    const float* be1    = (const float*)d_in[6];
    const float* W2     = (const float*)d_in[7];
    const float* b2     = (const float*)d_in[8];
    const float* g2     = (const float*)d_in[9];
    const float* be2    = (const float*)d_in[10];
    const float* W3     = (const float*)d_in[11];
    const float* b3     = (const float*)d_in[12];
    const float* bscale = (const float*)d_in[13];
    float* out = (float*)d_out;

    cudaFuncSetAttribute(gab_kernel, cudaFuncAttributeMaxDynamicSharedMemorySize,
                         (int)sizeof(Smem));
    dim3 grid(NP / PCHUNK, NG / 8, BATCH);
    gab_kernel<<<grid, 256, sizeof(Smem)>>>(scene, poses, W1, b1, g1, be1,
                                            W2, b2, g2, be2, W3, b3, bscale, out);
}

// round 7
// speedup vs baseline: 3.0997x; 1.2119x over previous
#include <cuda_runtime.h>
#include <cuda_fp16.h>
#include <cstdint>

// Problem dims (fixed by setup_inputs)
#define BATCH 4
#define NG 64
#define NH 8
#define NP 4096
#define PCHUNK 256
#define TILE 16
#define HP 68        // u32 pitch for h16; 68 % 32 == 4 -> conflict-free frag gathers

// Fixed-point scales for LN1 stats (validated)
#define SC1B 262144.f      // 2^18
#define SC2B 16384.f       // 2^14

struct __align__(16) Smem {
    uint4    Bp[8][8][32];        // W2 fp16 split {hi0,hi1,lo0,lo1}   32 KB
    float4   sp[PCHUNK];          // scene points                       4 KB
    float    b2s[64];             //                                   256 B
    uint32_t h16[8][TILE * HP];   // per-warp h1 as fp16x2           34.8 KB
};                                 // ~70.3 KB total

__device__ __forceinline__ int redux_s32(int v) {
    int r;
    asm("redux.sync.add.s32 %0, %1, 0xffffffff;" : "=r"(r) : "r"(v));
    return r;
}
// bf16 split (stage D only): pack (x0->low, x1->high); hi + residual lo.
__device__ __forceinline__ void split2(float x0, float x1, unsigned& hi, unsigned& lo) {
    asm("cvt.rn.bf16x2.f32 %0, %1, %2;" : "=r"(hi) : "f"(x1), "f"(x0));
    float h0 = __uint_as_float(hi << 16);
    float h1 = __uint_as_float(hi & 0xffff0000u);
    asm("cvt.rn.bf16x2.f32 %0, %1, %2;" : "=r"(lo) : "f"(x1 - h1), "f"(x0 - h0));
}
// fp16 split (W2/B operand): hi + residual lo, packed fp16x2 (x0 low).
__device__ __forceinline__ void split2h(float x0, float x1, unsigned& hi, unsigned& lo) {
    asm("cvt.rn.f16x2.f32 %0, %1, %2;" : "=r"(hi) : "f"(x1), "f"(x0));
    __half2 hv = *reinterpret_cast<__half2*>(&hi);
    float2 back = __half22float2(hv);
    asm("cvt.rn.f16x2.f32 %0, %1, %2;" : "=r"(lo) : "f"(x1 - back.y), "f"(x0 - back.x));
}
__device__ __forceinline__ unsigned pack_h2(float x0, float x1) {
    unsigned u;
    asm("cvt.rn.f16x2.f32 %0, %1, %2;" : "=r"(u) : "f"(x1), "f"(x0));
    return u;
}
__device__ __forceinline__ void mma_f16(float d[4], const unsigned a[4],
                                        unsigned b0, unsigned b1) {
    asm volatile(
        "mma.sync.aligned.m16n8k16.row.col.f32.f16.f16.f32 "
        "{%0,%1,%2,%3},{%4,%5,%6,%7},{%8,%9},{%0,%1,%2,%3};"
        : "+f"(d[0]), "+f"(d[1]), "+f"(d[2]), "+f"(d[3])
        : "r"(a[0]), "r"(a[1]), "r"(a[2]), "r"(a[3]), "r"(b0), "r"(b1));
}
__device__ __forceinline__ void mma_bf16(float d[4], const unsigned a[4],
                                         unsigned b0, unsigned b1) {
    asm volatile(
        "mma.sync.aligned.m16n8k16.row.col.f32.bf16.bf16.f32 "
        "{%0,%1,%2,%3},{%4,%5,%6,%7},{%8,%9},{%0,%1,%2,%3};"
        : "+f"(d[0]), "+f"(d[1]), "+f"(d[2]), "+f"(d[3])
        : "r"(a[0]), "r"(a[1]), "r"(a[2]), "r"(a[3]), "r"(b0), "r"(b1));
}

__global__ void __launch_bounds__(256, 2)
gab_kernel(const float* __restrict__ scene,   // (B, NP, 3)
           const float* __restrict__ poses,   // (B, NG, 7)
           const float* __restrict__ W1, const float* __restrict__ b1,
           const float* __restrict__ g1, const float* __restrict__ be1,
           const float* __restrict__ W2, const float* __restrict__ b2,
           const float* __restrict__ g2, const float* __restrict__ be2,
           const float* __restrict__ W3, const float* __restrict__ b3,
           const float* __restrict__ bscale,
           float* __restrict__ out)            // (B, NH, NG, NP)
{
    extern __shared__ __align__(16) char smraw[];
    Smem& sm = *reinterpret_cast<Smem*>(smraw);

    const int tid = threadIdx.x;
    const int b = blockIdx.z;
    const int gbase = blockIdx.y * 8;
    const int p0 = blockIdx.x * PCHUNK;

    // ---- Build fragment-ordered fp16-split W2 pack; stage b2/scene ----
    for (int idx = tid; idx < 8 * 8 * 32; idx += 256) {
        int kb = idx >> 8, rem = idx & 255;
        int nb = rem >> 5, ln = rem & 31;
        int tt = ln & 3, c = ln >> 2;
        int n = nb * 8 + c;
        int k0 = kb * 16 + 2 * tt;
        float w00 = W2[(k0 + 0) * 64 + n], w01 = W2[(k0 + 1) * 64 + n];
        float w10 = W2[(k0 + 8) * 64 + n], w11 = W2[(k0 + 9) * 64 + n];
        unsigned hi0, lo0, hi1, lo1;
        split2h(w00, w01, hi0, lo0);
        split2h(w10, w11, hi1, lo1);
        sm.Bp[kb][nb][ln] = make_uint4(hi0, hi1, lo0, lo1);
    }
    if (tid < 64) sm.b2s[tid] = b2[tid];
    if (tid < PCHUNK) {
        const float* spp = scene + ((size_t)b * NP + p0 + tid) * 3;
        sm.sp[tid] = make_float4(spp[0], spp[1], spp[2], 0.f);
    }
    __syncthreads();

    const int wid = tid >> 5, lane = tid & 31;
    const int g = gbase + wid;
    const int t = lane & 3, gg = lane >> 2;   // mma fragment coords

    // ---- Register-cached stage-B weights (lane owns h cols 4*lane..4*lane+3) ----
    const float4 w1f0 = __ldg((const float4*)W1 + lane);
    const float4 w1f1 = __ldg((const float4*)W1 + 32 + lane);
    const float4 w1f2 = __ldg((const float4*)W1 + 64 + lane);
    const float4 w1f3 = __ldg((const float4*)W1 + 96 + lane);
    const float4 b1q  = __ldg((const float4*)b1 + lane);
    const float4 g1q  = __ldg((const float4*)g1 + lane);
    const float4 be1q = __ldg((const float4*)be1 + lane);

    // ---- Stage-D B-fragments: A3 = g2 (*) W3, split bf16, n = gg ----
    unsigned bDh0[4], bDh1[4], bDl0[4], bDl1[4];
    #pragma unroll
    for (int kb2 = 0; kb2 < 4; ++kb2) {
        int k0 = kb2 * 16 + 2 * t;
        float a0 = __ldg(g2 + k0 + 0) * __ldg(W3 + (k0 + 0) * 8 + gg);
        float a1 = __ldg(g2 + k0 + 1) * __ldg(W3 + (k0 + 1) * 8 + gg);
        float a2 = __ldg(g2 + k0 + 8) * __ldg(W3 + (k0 + 8) * 8 + gg);
        float a3 = __ldg(g2 + k0 + 9) * __ldg(W3 + (k0 + 9) * 8 + gg);
        split2(a0, a1, bDh0[kb2], bDl0[kb2]);
        split2(a2, a3, bDh1[kb2], bDl1[kb2]);
    }

    // ---- Per-head fold constants for heads h0 = 2t, h1 = 2t+1 ----
    float K2a = 0.f, K2b = 0.f, K1a = 0.f, K1b = 0.f;
    #pragma unroll 8
    for (int c = 0; c < 64; ++c) {
        float2 w = *reinterpret_cast<const float2*>(W3 + c * 8 + 2 * t);
        float gc = __ldg(g2 + c), bc = __ldg(be2 + c);
        K2a = fmaf(gc, w.x, K2a); K2b = fmaf(gc, w.y, K2b);
        K1a = fmaf(bc, w.x, K1a); K1b = fmaf(bc, w.y, K1b);
    }
    const float bsa = __ldg(bscale + 2 * t), bsb = __ldg(bscale + 2 * t + 1);
    const float C0a = (K1a + __ldg(b3 + 2 * t)) * bsa;
    const float C0b = (K1b + __ldg(b3 + 2 * t + 1)) * bsb;

    // Per-warp pose -> rotation
    const float* pp = poses + ((size_t)(b * NG + g)) * 7;
    float tx = pp[0], ty = pp[1], tz = pp[2];
    float qx = pp[3], qy = pp[4], qz = pp[5], qw = pp[6];
    float inv = 1.f / (sqrtf(qx * qx + qy * qy + qz * qz + qw * qw) + 1e-8f);
    qx *= inv; qy *= inv; qz *= inv; qw *= inv;
    float xx = qx * qx, yy = qy * qy, zz = qz * qz;
    float xy = qx * qy, xz = qx * qz, yz = qy * qz;
    float wx = qw * qx, wy = qw * qy, wz = qw * qz;
    float R00 = 1.f - 2.f * (yy + zz), R01 = 2.f * (xy - wz), R02 = 2.f * (xz + wy);
    float R10 = 2.f * (xy + wz), R11 = 1.f - 2.f * (xx + zz), R12 = 2.f * (yz - wx);
    float R20 = 2.f * (xz - wy), R21 = 2.f * (yz + wx), R22 = 1.f - 2.f * (xx + yy);

    uint32_t* hw16 = sm.h16[wid];
    const size_t outbase = (((size_t)b * NH) * NG + g) * NP + p0;

    for (int it = 0; it < PCHUNK / TILE; ++it) {
        // ---- Stage B: 16 rows -> normalized h1, stored as fp16x2 ----
        #pragma unroll 2
        for (int r = 0; r < TILE; ++r) {
            float4 P = sm.sp[it * TILE + r];
            float rx = P.x - tx, ry = P.y - ty, rz = P.z - tz;
            float lx = R00 * rx + R10 * ry + R20 * rz;
            float ly = R01 * rx + R11 * ry + R21 * rz;
            float lz = R02 * rx + R12 * ry + R22 * rz;
            float dd = sqrtf(lx * lx + ly * ly + lz * lz);
            float a0 = fmaxf(fmaf(lx, w1f0.x, fmaf(ly, w1f1.x, fmaf(lz, w1f2.x, fmaf(dd, w1f3.x, b1q.x)))), 0.f);
            float a1 = fmaxf(fmaf(lx, w1f0.y, fmaf(ly, w1f1.y, fmaf(lz, w1f2.y, fmaf(dd, w1f3.y, b1q.y)))), 0.f);
            float a2 = fmaxf(fmaf(lx, w1f0.z, fmaf(ly, w1f1.z, fmaf(lz, w1f2.z, fmaf(dd, w1f3.z, b1q.z)))), 0.f);
            float a3 = fmaxf(fmaf(lx, w1f0.w, fmaf(ly, w1f1.w, fmaf(lz, w1f2.w, fmaf(dd, w1f3.w, b1q.w)))), 0.f);
            float s  = (a0 + a1) + (a2 + a3);
            float s2 = fmaf(a0, a0, fmaf(a1, a1, fmaf(a2, a2, a3 * a3)));
            int is = redux_s32(__float2int_rn(s * SC1B));
            int iq = redux_s32(__float2int_rn(s2 * SC2B));
            float mu  = (float)is * (1.f / (SC1B * 128.f));
            float ex2 = (float)iq * (1.f / (SC2B * 128.f));
            float rs = rsqrtf(fmaxf(ex2 - mu * mu, 0.f) + 1e-5f);
            float h0 = fmaf((a0 - mu) * rs, g1q.x, be1q.x);
            float h1 = fmaf((a1 - mu) * rs, g1q.y, be1q.y);
            float h2 = fmaf((a2 - mu) * rs, g1q.z, be1q.z);
            float h3 = fmaf((a3 - mu) * rs, g1q.w, be1q.w);
            unsigned u0 = pack_h2(h0, h1);
            unsigned u1 = pack_h2(h2, h3);
            *reinterpret_cast<uint2*>(hw16 + r * HP + 2 * lane) = make_uint2(u0, u1);
        }
        __syncwarp();

        // ---- Stage C: 16x64x128, fp16 A (single) x fp16 B (2-term) ----
        float d[8][4];
        #pragma unroll
        for (int nb = 0; nb < 8; ++nb) { d[nb][0] = d[nb][1] = d[nb][2] = d[nb][3] = 0.f; }

        #pragma unroll 2
        for (int kb = 0; kb < 8; ++kb) {
            unsigned afr[4];
            afr[0] = hw16[gg * HP + kb * 8 + t];
            afr[1] = hw16[(gg + 8) * HP + kb * 8 + t];
            afr[2] = hw16[gg * HP + kb * 8 + t + 4];
            afr[3] = hw16[(gg + 8) * HP + kb * 8 + t + 4];
            #pragma unroll
            for (int nb = 0; nb < 8; ++nb) {
                uint4 bp = sm.Bp[kb][nb][lane];
                mma_f16(d[nb], afr, bp.x, bp.y);   // A * Bhi
                mma_f16(d[nb], afr, bp.z, bp.w);   // A * Blo
            }
        }

        // ---- Fused epilogue + Stage D: v = relu(d+b2) -> bf16 split -> mma vs A3 ----
        float ddd[4] = {0.f, 0.f, 0.f, 0.f};
        float sg = 0.f, qg = 0.f, sh = 0.f, qh = 0.f;
        #pragma unroll
        for (int kb2 = 0; kb2 < 4; ++kb2) {
            const int nb0 = 2 * kb2, nb1 = 2 * kb2 + 1;
            float2 bb0 = *reinterpret_cast<const float2*>(sm.b2s + nb0 * 8 + 2 * t);
            float2 bb1 = *reinterpret_cast<const float2*>(sm.b2s + nb1 * 8 + 2 * t);
            float v00 = fmaxf(d[nb0][0] + bb0.x, 0.f), v01 = fmaxf(d[nb0][1] + bb0.y, 0.f);
            float v10 = fmaxf(d[nb0][2] + bb0.x, 0.f), v11 = fmaxf(d[nb0][3] + bb0.y, 0.f);
            float v20 = fmaxf(d[nb1][0] + bb1.x, 0.f), v21 = fmaxf(d[nb1][1] + bb1.y, 0.f);
            float v30 = fmaxf(d[nb1][2] + bb1.x, 0.f), v31 = fmaxf(d[nb1][3] + bb1.y, 0.f);
            sg += (v00 + v01) + (v20 + v21);
            qg = fmaf(v00, v00, fmaf(v01, v01, fmaf(v20, v20, fmaf(v21, v21, qg))));
            sh += (v10 + v11) + (v30 + v31);
            qh = fmaf(v10, v10, fmaf(v11, v11, fmaf(v30, v30, fmaf(v31, v31, qh))));
            unsigned ahi[4], alo[4];
            split2(v00, v01, ahi[0], alo[0]);
            split2(v10, v11, ahi[1], alo[1]);
            split2(v20, v21, ahi[2], alo[2]);
            split2(v30, v31, ahi[3], alo[3]);
            mma_bf16(ddd, ahi, bDh0[kb2], bDh1[kb2]);   // vhi * A3hi
            mma_bf16(ddd, alo, bDh0[kb2], bDh1[kb2]);   // vlo * A3hi
            mma_bf16(ddd, ahi, bDl0[kb2], bDl1[kb2]);   // vhi * A3lo
        }
        #pragma unroll
        for (int o = 1; o <= 2; o <<= 1) {
            sg += __shfl_xor_sync(0xffffffffu, sg, o);
            qg += __shfl_xor_sync(0xffffffffu, qg, o);
            sh += __shfl_xor_sync(0xffffffffu, sh, o);
            qh += __shfl_xor_sync(0xffffffffu, qh, o);
        }
        float muA = sg * (1.f / 64.f);
        float rsA = rsqrtf(fmaxf(qg * (1.f / 64.f) - muA * muA, 0.f) + 1e-5f);
        float muB = sh * (1.f / 64.f);
        float rsB = rsqrtf(fmaxf(qh * (1.f / 64.f) - muB * muB, 0.f) + 1e-5f);

        // fold LN2 and write directly: out = (S - mu*K2)*rs*bs + C0
        {
            const int pw = it * TILE;
            float* oA = out + outbase + (size_t)(2 * t) * (NG * NP) + pw;
            float* oB = out + outbase + (size_t)(2 * t + 1) * (NG * NP) + pw;
            float m1 = rsA * bsa, m2 = rsA * bsb;
            float m3 = rsB * bsa, m4 = rsB * bsb;
            oA[gg]     = fmaf(ddd[0], m1, fmaf(-muA * m1, K2a, C0a));
            oB[gg]     = fmaf(ddd[1], m2, fmaf(-muA * m2, K2b, C0b));
            oA[gg + 8] = fmaf(ddd[2], m3, fmaf(-muB * m3, K2a, C0a));
            oB[gg + 8] = fmaf(ddd[3], m4, fmaf(-muB * m4, K2b, C0b));
        }
        __syncwarp();   // protect h16 reuse across iterations
    }
}

extern "C" void kernel_launch(void* const* d_in, const int* in_sizes, int n_in,
                              void* d_out, int out_size) {
    // metadata order: grasp_tokens, scene_points, grasp_poses, W1, b1, g1, beta1,
    //                 W2, b2, g2, beta2, W3, b3, bias_scale
    const float* scene  = (const float*)d_in[1];
    const float* poses  = (const float*)d_in[2];
    const float* W1     = (const float*)d_in[3];
    const float* b1     = (const float*)d_in[4];
    const float* g1     = (const float*)d_in[5];
    const float* be1    = (const float*)d_in[6];
    const float* W2     = (const float*)d_in[7];
    const float* b2     = (const float*)d_in[8];
    const float* g2     = (const float*)d_in[9];
    const float* be2    = (const float*)d_in[10];
    const float* W3     = (const float*)d_in[11];
    const float* b3     = (const float*)d_in[12];
    const float* bscale = (const float*)d_in[13];
    float* out = (float*)d_out;

    cudaFuncSetAttribute(gab_kernel, cudaFuncAttributeMaxDynamicSharedMemorySize,
                         (int)sizeof(Smem));
    dim3 grid(NP / PCHUNK, NG / 8, BATCH);
    gab_kernel<<<grid, 256, sizeof(Smem)>>>(scene, poses, W1, b1, g1, be1,
                                            W2, b2, g2, be2, W3, b3, bscale, out);
}

// round 8
// speedup vs baseline: 3.7043x; 1.1950x over previous
#include <cuda_runtime.h>
#include <cuda_fp16.h>
#include <cstdint>

// Problem dims (fixed by setup_inputs)
#define BATCH 4
#define NG 64
#define NH 8
#define NP 4096
#define PCHUNK 256
#define TILE 16
#define HP 68        // u32 pitch for h16; 68 % 32 == 4 -> conflict-free frag gathers

// Fixed-point scales for LN1 stats (validated)
#define SC1B 262144.f      // 2^18
#define SC2B 16384.f       // 2^14

struct __align__(16) Smem {
    uint2    Bp[8][8][32];        // W2 fp16 {hi0,hi1} fragments       16 KB
    float4   sp[PCHUNK];          // scene points                       4 KB
    float    b2s[64];             //                                   256 B
    uint32_t h16[8][TILE * HP];   // per-warp h1 as fp16x2           34.8 KB
};                                 // ~55 KB total

__device__ __forceinline__ int redux_s32(int v) {
    int r;
    asm("redux.sync.add.s32 %0, %1, 0xffffffff;" : "=r"(r) : "r"(v));
    return r;
}
// fp16 split: hi + residual lo, packed fp16x2 (x0 low).
__device__ __forceinline__ void split2h(float x0, float x1, unsigned& hi, unsigned& lo) {
    asm("cvt.rn.f16x2.f32 %0, %1, %2;" : "=r"(hi) : "f"(x1), "f"(x0));
    __half2 hv = *reinterpret_cast<__half2*>(&hi);
    float2 back = __half22float2(hv);
    asm("cvt.rn.f16x2.f32 %0, %1, %2;" : "=r"(lo) : "f"(x1 - back.y), "f"(x0 - back.x));
}
__device__ __forceinline__ unsigned pack_h2(float x0, float x1) {
    unsigned u;
    asm("cvt.rn.f16x2.f32 %0, %1, %2;" : "=r"(u) : "f"(x1), "f"(x0));
    return u;
}
__device__ __forceinline__ void mma_f16(float d[4], const unsigned a[4],
                                        unsigned b0, unsigned b1) {
    asm volatile(
        "mma.sync.aligned.m16n8k16.row.col.f32.f16.f16.f32 "
        "{%0,%1,%2,%3},{%4,%5,%6,%7},{%8,%9},{%0,%1,%2,%3};"
        : "+f"(d[0]), "+f"(d[1]), "+f"(d[2]), "+f"(d[3])
        : "r"(a[0]), "r"(a[1]), "r"(a[2]), "r"(a[3]), "r"(b0), "r"(b1));
}

__global__ void __launch_bounds__(256, 2)
gab_kernel(const float* __restrict__ scene,   // (B, NP, 3)
           const float* __restrict__ poses,   // (B, NG, 7)
           const float* __restrict__ W1, const float* __restrict__ b1,
           const float* __restrict__ g1, const float* __restrict__ be1,
           const float* __restrict__ W2, const float* __restrict__ b2,
           const float* __restrict__ g2, const float* __restrict__ be2,
           const float* __restrict__ W3, const float* __restrict__ b3,
           const float* __restrict__ bscale,
           float* __restrict__ out)            // (B, NH, NG, NP)
{
    extern __shared__ __align__(16) char smraw[];
    Smem& sm = *reinterpret_cast<Smem*>(smraw);

    const int tid = threadIdx.x;
    const int b = blockIdx.z;
    const int gbase = blockIdx.y * 8;
    const int p0 = blockIdx.x * PCHUNK;

    // ---- Build fragment-ordered fp16 W2 pack (hi only); stage b2/scene ----
    for (int idx = tid; idx < 8 * 8 * 32; idx += 256) {
        int kb = idx >> 8, rem = idx & 255;
        int nb = rem >> 5, ln = rem & 31;
        int tt = ln & 3, c = ln >> 2;
        int n = nb * 8 + c;
        int k0 = kb * 16 + 2 * tt;
        unsigned hi0 = pack_h2(W2[(k0 + 0) * 64 + n], W2[(k0 + 1) * 64 + n]);
        unsigned hi1 = pack_h2(W2[(k0 + 8) * 64 + n], W2[(k0 + 9) * 64 + n]);
        sm.Bp[kb][nb][ln] = make_uint2(hi0, hi1);
    }
    if (tid < 64) sm.b2s[tid] = b2[tid];
    if (tid < PCHUNK) {
        const float* spp = scene + ((size_t)b * NP + p0 + tid) * 3;
        sm.sp[tid] = make_float4(spp[0], spp[1], spp[2], 0.f);
    }
    __syncthreads();

    const int wid = tid >> 5, lane = tid & 31;
    const int g = gbase + wid;
    const int t = lane & 3, gg = lane >> 2;   // mma fragment coords

    // ---- Register-cached stage-B weights (lane owns h cols 4*lane..4*lane+3) ----
    const float4 w1f0 = __ldg((const float4*)W1 + lane);
    const float4 w1f1 = __ldg((const float4*)W1 + 32 + lane);
    const float4 w1f2 = __ldg((const float4*)W1 + 64 + lane);
    const float4 w1f3 = __ldg((const float4*)W1 + 96 + lane);
    const float4 b1q  = __ldg((const float4*)b1 + lane);
    const float4 g1q  = __ldg((const float4*)g1 + lane);
    const float4 be1q = __ldg((const float4*)be1 + lane);

    // ---- Stage-D B-fragments: A3 = g2 (*) W3, 2-term fp16, n = gg ----
    unsigned bDh0[4], bDh1[4], bDl0[4], bDl1[4];
    #pragma unroll
    for (int kb2 = 0; kb2 < 4; ++kb2) {
        int k0 = kb2 * 16 + 2 * t;
        float a0 = __ldg(g2 + k0 + 0) * __ldg(W3 + (k0 + 0) * 8 + gg);
        float a1 = __ldg(g2 + k0 + 1) * __ldg(W3 + (k0 + 1) * 8 + gg);
        float a2 = __ldg(g2 + k0 + 8) * __ldg(W3 + (k0 + 8) * 8 + gg);
        float a3 = __ldg(g2 + k0 + 9) * __ldg(W3 + (k0 + 9) * 8 + gg);
        split2h(a0, a1, bDh0[kb2], bDl0[kb2]);
        split2h(a2, a3, bDh1[kb2], bDl1[kb2]);
    }

    // ---- Per-head fold constants for heads h0 = 2t, h1 = 2t+1 ----
    float K2a = 0.f, K2b = 0.f, K1a = 0.f, K1b = 0.f;
    #pragma unroll 8
    for (int c = 0; c < 64; ++c) {
        float2 w = *reinterpret_cast<const float2*>(W3 + c * 8 + 2 * t);
        float gc = __ldg(g2 + c), bc = __ldg(be2 + c);
        K2a = fmaf(gc, w.x, K2a); K2b = fmaf(gc, w.y, K2b);
        K1a = fmaf(bc, w.x, K1a); K1b = fmaf(bc, w.y, K1b);
    }
    const float bsa = __ldg(bscale + 2 * t), bsb = __ldg(bscale + 2 * t + 1);
    const float C0a = (K1a + __ldg(b3 + 2 * t)) * bsa;
    const float C0b = (K1b + __ldg(b3 + 2 * t + 1)) * bsb;

    // Per-warp pose -> rotation
    const float* pp = poses + ((size_t)(b * NG + g)) * 7;
    float tx = pp[0], ty = pp[1], tz = pp[2];
    float qx = pp[3], qy = pp[4], qz = pp[5], qw = pp[6];
    float inv = 1.f / (sqrtf(qx * qx + qy * qy + qz * qz + qw * qw) + 1e-8f);
    qx *= inv; qy *= inv; qz *= inv; qw *= inv;
    float xx = qx * qx, yy = qy * qy, zz = qz * qz;
    float xy = qx * qy, xz = qx * qz, yz = qy * qz;
    float wx = qw * qx, wy = qw * qy, wz = qw * qz;
    float R00 = 1.f - 2.f * (yy + zz), R01 = 2.f * (xy - wz), R02 = 2.f * (xz + wy);
    float R10 = 2.f * (xy + wz), R11 = 1.f - 2.f * (xx + zz), R12 = 2.f * (yz - wx);
    float R20 = 2.f * (xz - wy), R21 = 2.f * (yz + wx), R22 = 1.f - 2.f * (xx + yy);

    uint32_t* hw16 = sm.h16[wid];
    const size_t outbase = (((size_t)b * NH) * NG + g) * NP + p0;

    for (int it = 0; it < PCHUNK / TILE; ++it) {
        // ---- Stage B: 16 rows -> normalized h1, stored as fp16x2 ----
        #pragma unroll 2
        for (int r = 0; r < TILE; ++r) {
            float4 P = sm.sp[it * TILE + r];
            float rx = P.x - tx, ry = P.y - ty, rz = P.z - tz;
            float lx = R00 * rx + R10 * ry + R20 * rz;
            float ly = R01 * rx + R11 * ry + R21 * rz;
            float lz = R02 * rx + R12 * ry + R22 * rz;
            float dd = sqrtf(lx * lx + ly * ly + lz * lz);
            float a0 = fmaxf(fmaf(lx, w1f0.x, fmaf(ly, w1f1.x, fmaf(lz, w1f2.x, fmaf(dd, w1f3.x, b1q.x)))), 0.f);
            float a1 = fmaxf(fmaf(lx, w1f0.y, fmaf(ly, w1f1.y, fmaf(lz, w1f2.y, fmaf(dd, w1f3.y, b1q.y)))), 0.f);
            float a2 = fmaxf(fmaf(lx, w1f0.z, fmaf(ly, w1f1.z, fmaf(lz, w1f2.z, fmaf(dd, w1f3.z, b1q.z)))), 0.f);
            float a3 = fmaxf(fmaf(lx, w1f0.w, fmaf(ly, w1f1.w, fmaf(lz, w1f2.w, fmaf(dd, w1f3.w, b1q.w)))), 0.f);
            float s  = (a0 + a1) + (a2 + a3);
            float s2 = fmaf(a0, a0, fmaf(a1, a1, fmaf(a2, a2, a3 * a3)));
            int is = redux_s32(__float2int_rn(s * SC1B));
            int iq = redux_s32(__float2int_rn(s2 * SC2B));
            float mu  = (float)is * (1.f / (SC1B * 128.f));
            float ex2 = (float)iq * (1.f / (SC2B * 128.f));
            float rs = rsqrtf(fmaxf(ex2 - mu * mu, 0.f) + 1e-5f);
            float h0 = fmaf((a0 - mu) * rs, g1q.x, be1q.x);
            float h1 = fmaf((a1 - mu) * rs, g1q.y, be1q.y);
            float h2 = fmaf((a2 - mu) * rs, g1q.z, be1q.z);
            float h3 = fmaf((a3 - mu) * rs, g1q.w, be1q.w);
            unsigned u0 = pack_h2(h0, h1);
            unsigned u1 = pack_h2(h2, h3);
            *reinterpret_cast<uint2*>(hw16 + r * HP + 2 * lane) = make_uint2(u0, u1);
        }
        __syncwarp();

        // ---- Stage C: 16x64x128, fp16 A x fp16 B (both single-term) ----
        float d[8][4];
        #pragma unroll
        for (int nb = 0; nb < 8; ++nb) { d[nb][0] = d[nb][1] = d[nb][2] = d[nb][3] = 0.f; }

        #pragma unroll 2
        for (int kb = 0; kb < 8; ++kb) {
            unsigned afr[4];
            afr[0] = hw16[gg * HP + kb * 8 + t];
            afr[1] = hw16[(gg + 8) * HP + kb * 8 + t];
            afr[2] = hw16[gg * HP + kb * 8 + t + 4];
            afr[3] = hw16[(gg + 8) * HP + kb * 8 + t + 4];
            #pragma unroll
            for (int nb = 0; nb < 8; ++nb) {
                uint2 bp = sm.Bp[kb][nb][lane];
                mma_f16(d[nb], afr, bp.x, bp.y);
            }
        }

        // ---- Fused epilogue + Stage D: v = relu(d+b2) -> fp16 -> mma vs A3 (2-term) ----
        float ddd[4] = {0.f, 0.f, 0.f, 0.f};
        float sg = 0.f, qg = 0.f, sh = 0.f, qh = 0.f;
        #pragma unroll
        for (int kb2 = 0; kb2 < 4; ++kb2) {
            const int nb0 = 2 * kb2, nb1 = 2 * kb2 + 1;
            float2 bb0 = *reinterpret_cast<const float2*>(sm.b2s + nb0 * 8 + 2 * t);
            float2 bb1 = *reinterpret_cast<const float2*>(sm.b2s + nb1 * 8 + 2 * t);
            float v00 = fmaxf(d[nb0][0] + bb0.x, 0.f), v01 = fmaxf(d[nb0][1] + bb0.y, 0.f);
            float v10 = fmaxf(d[nb0][2] + bb0.x, 0.f), v11 = fmaxf(d[nb0][3] + bb0.y, 0.f);
            float v20 = fmaxf(d[nb1][0] + bb1.x, 0.f), v21 = fmaxf(d[nb1][1] + bb1.y, 0.f);
            float v30 = fmaxf(d[nb1][2] + bb1.x, 0.f), v31 = fmaxf(d[nb1][3] + bb1.y, 0.f);
            sg += (v00 + v01) + (v20 + v21);
            qg = fmaf(v00, v00, fmaf(v01, v01, fmaf(v20, v20, fmaf(v21, v21, qg))));
            sh += (v10 + v11) + (v30 + v31);
            qh = fmaf(v10, v10, fmaf(v11, v11, fmaf(v30, v30, fmaf(v31, v31, qh))));
            unsigned av[4];
            av[0] = pack_h2(v00, v01);
            av[1] = pack_h2(v10, v11);
            av[2] = pack_h2(v20, v21);
            av[3] = pack_h2(v30, v31);
            mma_f16(ddd, av, bDh0[kb2], bDh1[kb2]);   // v * A3hi
            mma_f16(ddd, av, bDl0[kb2], bDl1[kb2]);   // v * A3lo
        }
        #pragma unroll
        for (int o = 1; o <= 2; o <<= 1) {
            sg += __shfl_xor_sync(0xffffffffu, sg, o);
            qg += __shfl_xor_sync(0xffffffffu, qg, o);
            sh += __shfl_xor_sync(0xffffffffu, sh, o);
            qh += __shfl_xor_sync(0xffffffffu, qh, o);
        }
        float muA = sg * (1.f / 64.f);
        float rsA = rsqrtf(fmaxf(qg * (1.f / 64.f) - muA * muA, 0.f) + 1e-5f);
        float muB = sh * (1.f / 64.f);
        float rsB = rsqrtf(fmaxf(qh * (1.f / 64.f) - muB * muB, 0.f) + 1e-5f);

        // fold LN2 and write directly: out = (S - mu*K2)*rs*bs + C0
        {
            const int pw = it * TILE;
            float* oA = out + outbase + (size_t)(2 * t) * (NG * NP) + pw;
            float* oB = out + outbase + (size_t)(2 * t + 1) * (NG * NP) + pw;
            float m1 = rsA * bsa, m2 = rsA * bsb;
            float m3 = rsB * bsa, m4 = rsB * bsb;
            oA[gg]     = fmaf(ddd[0], m1, fmaf(-muA * m1, K2a, C0a));
            oB[gg]     = fmaf(ddd[1], m2, fmaf(-muA * m2, K2b, C0b));
            oA[gg + 8] = fmaf(ddd[2], m3, fmaf(-muB * m3, K2a, C0a));
            oB[gg + 8] = fmaf(ddd[3], m4, fmaf(-muB * m4, K2b, C0b));
        }
        __syncwarp();   // protect h16 reuse across iterations
    }
}

extern "C" void kernel_launch(void* const* d_in, const int* in_sizes, int n_in,
                              void* d_out, int out_size) {
    // metadata order: grasp_tokens, scene_points, grasp_poses, W1, b1, g1, beta1,
    //                 W2, b2, g2, beta2, W3, b3, bias_scale
    const float* scene  = (const float*)d_in[1];
    const float* poses  = (const float*)d_in[2];
    const float* W1     = (const float*)d_in[3];
    const float* b1     = (const float*)d_in[4];
    const float* g1     = (const float*)d_in[5];
    const float* be1    = (const float*)d_in[6];
    const float* W2     = (const float*)d_in[7];
    const float* b2     = (const float*)d_in[8];
    const float* g2     = (const float*)d_in[9];
    const float* be2    = (const float*)d_in[10];
    const float* W3     = (const float*)d_in[11];
    const float* b3     = (const float*)d_in[12];
    const float* bscale = (const float*)d_in[13];
    float* out = (float*)d_out;

    cudaFuncSetAttribute(gab_kernel, cudaFuncAttributeMaxDynamicSharedMemorySize,
                         (int)sizeof(Smem));
    dim3 grid(NP / PCHUNK, NG / 8, BATCH);
    gab_kernel<<<grid, 256, sizeof(Smem)>>>(scene, poses, W1, b1, g1, be1,
                                            W2, b2, g2, be2, W3, b3, bscale, out);
}

// round 9
// speedup vs baseline: 6.1511x; 1.6605x over previous
#include <cuda_runtime.h>
#include <cuda_fp16.h>
#include <cstdint>

// Problem dims (fixed by setup_inputs)
#define BATCH 4
#define NG 64
#define NH 8
#define NP 4096
#define PCHUNK 256
#define TILE 16

struct __align__(16) Smem {
    uint2  Bp[8][8][32];      // W2' = diag(g1)*W2, fp16 frags {b0,b1}   16 KB
    uint2  W1p[16][32];       // W1' = [W1;b1;0] 2-term fp16 k8 frags     4 KB
    float4 sp[PCHUNK];        // scene points                             4 KB
    float  Gs[64];            // G[n]  = g1^T W2[:,n]                    256 B
    float  EBs[64];           // EB[n] = be1^T W2[:,n] + b2[n]           256 B
};                             // ~24.5 KB total

// fp16 split: hi + residual lo, packed fp16x2 (x0 low).
__device__ __forceinline__ void split2h(float x0, float x1, unsigned& hi, unsigned& lo) {
    asm("cvt.rn.f16x2.f32 %0, %1, %2;" : "=r"(hi) : "f"(x1), "f"(x0));
    __half2 hv = *reinterpret_cast<__half2*>(&hi);
    float2 back = __half22float2(hv);
    asm("cvt.rn.f16x2.f32 %0, %1, %2;" : "=r"(lo) : "f"(x1 - back.y), "f"(x0 - back.x));
}
__device__ __forceinline__ unsigned pack_h2(float x0, float x1) {
    unsigned u;
    asm("cvt.rn.f16x2.f32 %0, %1, %2;" : "=r"(u) : "f"(x1), "f"(x0));
    return u;
}
__device__ __forceinline__ float2 unpack_h2(unsigned u) {
    return __half22float2(*reinterpret_cast<__half2*>(&u));
}
__device__ __forceinline__ void mma_f16(float d[4], const unsigned a[4],
                                        unsigned b0, unsigned b1) {
    asm volatile(
        "mma.sync.aligned.m16n8k16.row.col.f32.f16.f16.f32 "
        "{%0,%1,%2,%3},{%4,%5,%6,%7},{%8,%9},{%0,%1,%2,%3};"
        : "+f"(d[0]), "+f"(d[1]), "+f"(d[2]), "+f"(d[3])
        : "r"(a[0]), "r"(a[1]), "r"(a[2]), "r"(a[3]), "r"(b0), "r"(b1));
}
__device__ __forceinline__ void mma_f16_k8(float d[4], unsigned a0, unsigned a1,
                                           unsigned b0) {
    asm volatile(
        "mma.sync.aligned.m16n8k8.row.col.f32.f16.f16.f32 "
        "{%0,%1,%2,%3},{%4,%5},{%6},{%0,%1,%2,%3};"
        : "+f"(d[0]), "+f"(d[1]), "+f"(d[2]), "+f"(d[3])
        : "r"(a0), "r"(a1), "r"(b0));
}

__global__ void __launch_bounds__(256, 2)
gab_kernel(const float* __restrict__ scene,   // (B, NP, 3)
           const float* __restrict__ poses,   // (B, NG, 7)
           const float* __restrict__ W1, const float* __restrict__ b1,
           const float* __restrict__ g1, const float* __restrict__ be1,
           const float* __restrict__ W2, const float* __restrict__ b2,
           const float* __restrict__ g2, const float* __restrict__ be2,
           const float* __restrict__ W3, const float* __restrict__ b3,
           const float* __restrict__ bscale,
           float* __restrict__ out)            // (B, NH, NG, NP)
{
    extern __shared__ __align__(16) char smraw[];
    Smem& sm = *reinterpret_cast<Smem*>(smraw);

    const int tid = threadIdx.x;
    const int b = blockIdx.z;
    const int gbase = blockIdx.y * 8;
    const int p0 = blockIdx.x * PCHUNK;

    // ---- Prologue: W2' frags, W1' frags, G/EB vectors, scene chunk ----
    for (int idx = tid; idx < 8 * 8 * 32; idx += 256) {
        int kb = idx >> 8, rem = idx & 255;
        int nb = rem >> 5, ln = rem & 31;
        int tt = ln & 3, c = ln >> 2;
        int n = nb * 8 + c;
        int k0 = kb * 16 + 2 * tt;
        unsigned hi0 = pack_h2(g1[k0 + 0] * W2[(k0 + 0) * 64 + n],
                               g1[k0 + 1] * W2[(k0 + 1) * 64 + n]);
        unsigned hi1 = pack_h2(g1[k0 + 8] * W2[(k0 + 8) * 64 + n],
                               g1[k0 + 9] * W2[(k0 + 9) * 64 + n]);
        sm.Bp[kb][nb][ln] = make_uint2(hi0, hi1);
    }
    for (int idx = tid; idx < 16 * 32; idx += 256) {
        int nb = idx >> 5, ln = idx & 31;
        int tt = ln & 3, c = ln >> 2;
        int n = nb * 8 + c;
        // W1' rows: 0-3 = W1, 4 = b1, 5-7 = 0
        int k0 = 2 * tt, k1 = 2 * tt + 1;
        float w0 = (k0 < 4) ? W1[k0 * 128 + n] : (k0 == 4 ? b1[n] : 0.f);
        float w1 = (k1 < 4) ? W1[k1 * 128 + n] : (k1 == 4 ? b1[n] : 0.f);
        unsigned hi, lo;
        split2h(w0, w1, hi, lo);
        sm.W1p[nb][ln] = make_uint2(hi, lo);
    }
    if (tid < 64) {
        float G = 0.f, E = 0.f;
        #pragma unroll 8
        for (int k = 0; k < 128; ++k) {
            float w = W2[k * 64 + tid];
            G = fmaf(g1[k], w, G);
            E = fmaf(be1[k], w, E);
        }
        sm.Gs[tid] = G;
        sm.EBs[tid] = E + b2[tid];
    }
    if (tid < PCHUNK) {
        const float* spp = scene + ((size_t)b * NP + p0 + tid) * 3;
        sm.sp[tid] = make_float4(spp[0], spp[1], spp[2], 0.f);
    }
    __syncthreads();

    const int wid = tid >> 5, lane = tid & 31;
    const int g = gbase + wid;
    const int t = lane & 3, gg = lane >> 2;   // mma fragment coords

    // ---- G/EB register cache (fp16x2 per nb, cols 2t,2t+1) ----
    unsigned Greg[8], EBreg[8];
    #pragma unroll
    for (int nb = 0; nb < 8; ++nb) {
        Greg[nb]  = pack_h2(sm.Gs[nb * 8 + 2 * t],  sm.Gs[nb * 8 + 2 * t + 1]);
        EBreg[nb] = pack_h2(sm.EBs[nb * 8 + 2 * t], sm.EBs[nb * 8 + 2 * t + 1]);
    }

    // ---- Stage-D B-fragments: A3 = g2 (*) W3, 2-term fp16, n = gg ----
    unsigned bDh0[4], bDh1[4], bDl0[4], bDl1[4];
    #pragma unroll
    for (int kb2 = 0; kb2 < 4; ++kb2) {
        int k0 = kb2 * 16 + 2 * t;
        float a0 = __ldg(g2 + k0 + 0) * __ldg(W3 + (k0 + 0) * 8 + gg);
        float a1 = __ldg(g2 + k0 + 1) * __ldg(W3 + (k0 + 1) * 8 + gg);
        float a2 = __ldg(g2 + k0 + 8) * __ldg(W3 + (k0 + 8) * 8 + gg);
        float a3 = __ldg(g2 + k0 + 9) * __ldg(W3 + (k0 + 9) * 8 + gg);
        split2h(a0, a1, bDh0[kb2], bDl0[kb2]);
        split2h(a2, a3, bDh1[kb2], bDl1[kb2]);
    }

    // ---- Per-head fold constants for heads h0 = 2t, h1 = 2t+1 ----
    float K2a = 0.f, K2b = 0.f, K1a = 0.f, K1b = 0.f;
    #pragma unroll 8
    for (int c = 0; c < 64; ++c) {
        float2 w = *reinterpret_cast<const float2*>(W3 + c * 8 + 2 * t);
        float gc = __ldg(g2 + c), bc = __ldg(be2 + c);
        K2a = fmaf(gc, w.x, K2a); K2b = fmaf(gc, w.y, K2b);
        K1a = fmaf(bc, w.x, K1a); K1b = fmaf(bc, w.y, K1b);
    }
    const float bsa = __ldg(bscale + 2 * t), bsb = __ldg(bscale + 2 * t + 1);
    const float C0a = (K1a + __ldg(b3 + 2 * t)) * bsa;
    const float C0b = (K1b + __ldg(b3 + 2 * t + 1)) * bsb;

    // Per-warp pose -> rotation
    const float* pp = poses + ((size_t)(b * NG + g)) * 7;
    float tx = pp[0], ty = pp[1], tz = pp[2];
    float qx = pp[3], qy = pp[4], qz = pp[5], qw = pp[6];
    float inv = 1.f / (sqrtf(qx * qx + qy * qy + qz * qz + qw * qw) + 1e-8f);
    qx *= inv; qy *= inv; qz *= inv; qw *= inv;
    float xx = qx * qx, yy = qy * qy, zz = qz * qz;
    float xy = qx * qy, xz = qx * qz, yz = qy * qz;
    float wx = qw * qx, wy = qw * qy, wz = qw * qz;
    float R00 = 1.f - 2.f * (yy + zz), R01 = 2.f * (xy - wz), R02 = 2.f * (xz + wy);
    float R10 = 2.f * (xy + wz), R11 = 1.f - 2.f * (xx + zz), R12 = 2.f * (yz - wx);
    float R20 = 2.f * (xz - wy), R21 = 2.f * (yz + wx), R22 = 1.f - 2.f * (xx + yy);

    const size_t outbase = (((size_t)b * NH) * NG + g) * NP + p0;

    for (int it = 0; it < PCHUNK / TILE; ++it) {
        // ---- Geometry for this lane's two rows (gg, gg+8) ----
        float4 PA = sm.sp[it * TILE + gg];
        float4 PB = sm.sp[it * TILE + gg + 8];
        float rxA = PA.x - tx, ryA = PA.y - ty, rzA = PA.z - tz;
        float lxA = R00 * rxA + R10 * ryA + R20 * rzA;
        float lyA = R01 * rxA + R11 * ryA + R21 * rzA;
        float lzA = R02 * rxA + R12 * ryA + R22 * rzA;
        float ddA = sqrtf(lxA * lxA + lyA * lyA + lzA * lzA);
        float rxB = PB.x - tx, ryB = PB.y - ty, rzB = PB.z - tz;
        float lxB = R00 * rxB + R10 * ryB + R20 * rzB;
        float lyB = R01 * rxB + R11 * ryB + R21 * rzB;
        float lzB = R02 * rxB + R12 * ryB + R22 * rzB;
        float ddB = sqrtf(lxB * lxB + lyB * lyB + lzB * lzB);
        // A-frag (m16n8k8): k cols 2t,2t+1 of feats = (lx,ly,lz,dd,1,0,0,0)
        float s0A = (t == 0) ? lxA : (t == 1) ? lzA : (t == 2) ? 1.f : 0.f;
        float s1A = (t == 0) ? lyA : (t == 1) ? ddA : 0.f;
        float s0B = (t == 0) ? lxB : (t == 1) ? lzB : (t == 2) ? 1.f : 0.f;
        float s1B = (t == 0) ? lyB : (t == 1) ? ddB : 0.f;
        unsigned af0 = pack_h2(s0A, s1A);
        unsigned af1 = pack_h2(s0B, s1B);

        // ---- Stage B: a = relu(feats @ W1' ) via 16x m16n8k8 (2-term W1) ----
        unsigned afr[8][4];
        float sA = 0.f, qA = 0.f, sB = 0.f, qB = 0.f;
        #pragma unroll
        for (int nb = 0; nb < 16; ++nb) {
            uint2 wb = sm.W1p[nb][lane];
            float dB[4] = {0.f, 0.f, 0.f, 0.f};
            mma_f16_k8(dB, af0, af1, wb.x);
            mma_f16_k8(dB, af0, af1, wb.y);
            float v0 = fmaxf(dB[0], 0.f), v1 = fmaxf(dB[1], 0.f);
            float v2 = fmaxf(dB[2], 0.f), v3 = fmaxf(dB[3], 0.f);
            sA += v0 + v1; qA = fmaf(v0, v0, fmaf(v1, v1, qA));
            sB += v2 + v3; qB = fmaf(v2, v2, fmaf(v3, v3, qB));
            afr[nb >> 1][(nb & 1) ? 2 : 0] = pack_h2(v0, v1);
            afr[nb >> 1][(nb & 1) ? 3 : 1] = pack_h2(v2, v3);
        }
        // LN1 stats over 128 cols: reduce across t-quad
        #pragma unroll
        for (int o = 1; o <= 2; o <<= 1) {
            sA += __shfl_xor_sync(0xffffffffu, sA, o);
            qA += __shfl_xor_sync(0xffffffffu, qA, o);
            sB += __shfl_xor_sync(0xffffffffu, sB, o);
            qB += __shfl_xor_sync(0xffffffffu, qB, o);
        }
        float mu1A = sA * (1.f / 128.f);
        float rs1A = rsqrtf(fmaxf(qA * (1.f / 128.f) - mu1A * mu1A, 0.f) + 1e-5f);
        float ng1A = -mu1A * rs1A;
        float mu1B = sB * (1.f / 128.f);
        float rs1B = rsqrtf(fmaxf(qB * (1.f / 128.f) - mu1B * mu1B, 0.f) + 1e-5f);
        float ng1B = -mu1B * rs1B;

        // ---- Stage C: a16 @ W2' (single fp16 both sides) ----
        float d[8][4];
        #pragma unroll
        for (int nb = 0; nb < 8; ++nb) { d[nb][0] = d[nb][1] = d[nb][2] = d[nb][3] = 0.f; }
        #pragma unroll
        for (int kb = 0; kb < 8; ++kb) {
            #pragma unroll
            for (int nb = 0; nb < 8; ++nb) {
                uint2 bp = sm.Bp[kb][nb][lane];
                mma_f16(d[nb], afr[kb], bp.x, bp.y);
            }
        }

        // ---- Epilogue (LN1-fold) + Stage D chaining ----
        float ddd[4] = {0.f, 0.f, 0.f, 0.f};
        float sg = 0.f, qg = 0.f, sh = 0.f, qh = 0.f;
        #pragma unroll
        for (int kb2 = 0; kb2 < 4; ++kb2) {
            const int nb0 = 2 * kb2, nb1 = 2 * kb2 + 1;
            float2 G0 = unpack_h2(Greg[nb0]), E0 = unpack_h2(EBreg[nb0]);
            float2 G1 = unpack_h2(Greg[nb1]), E1 = unpack_h2(EBreg[nb1]);
            // v = relu(rs1*d + ng1*G + EB)
            float v00 = fmaxf(fmaf(rs1A, d[nb0][0], fmaf(ng1A, G0.x, E0.x)), 0.f);
            float v01 = fmaxf(fmaf(rs1A, d[nb0][1], fmaf(ng1A, G0.y, E0.y)), 0.f);
            float v10 = fmaxf(fmaf(rs1B, d[nb0][2], fmaf(ng1B, G0.x, E0.x)), 0.f);
            float v11 = fmaxf(fmaf(rs1B, d[nb0][3], fmaf(ng1B, G0.y, E0.y)), 0.f);
            float v20 = fmaxf(fmaf(rs1A, d[nb1][0], fmaf(ng1A, G1.x, E1.x)), 0.f);
            float v21 = fmaxf(fmaf(rs1A, d[nb1][1], fmaf(ng1A, G1.y, E1.y)), 0.f);
            float v30 = fmaxf(fmaf(rs1B, d[nb1][2], fmaf(ng1B, G1.x, E1.x)), 0.f);
            float v31 = fmaxf(fmaf(rs1B, d[nb1][3], fmaf(ng1B, G1.y, E1.y)), 0.f);
            sg += (v00 + v01) + (v20 + v21);
            qg = fmaf(v00, v00, fmaf(v01, v01, fmaf(v20, v20, fmaf(v21, v21, qg))));
            sh += (v10 + v11) + (v30 + v31);
            qh = fmaf(v10, v10, fmaf(v11, v11, fmaf(v30, v30, fmaf(v31, v31, qh))));
            unsigned av[4];
            av[0] = pack_h2(v00, v01);
            av[1] = pack_h2(v10, v11);
            av[2] = pack_h2(v20, v21);
            av[3] = pack_h2(v30, v31);
            mma_f16(ddd, av, bDh0[kb2], bDh1[kb2]);   // v * A3hi
            mma_f16(ddd, av, bDl0[kb2], bDl1[kb2]);   // v * A3lo
        }
        #pragma unroll
        for (int o = 1; o <= 2; o <<= 1) {
            sg += __shfl_xor_sync(0xffffffffu, sg, o);
            qg += __shfl_xor_sync(0xffffffffu, qg, o);
            sh += __shfl_xor_sync(0xffffffffu, sh, o);
            qh += __shfl_xor_sync(0xffffffffu, qh, o);
        }
        float muA = sg * (1.f / 64.f);
        float rsA = rsqrtf(fmaxf(qg * (1.f / 64.f) - muA * muA, 0.f) + 1e-5f);
        float muB = sh * (1.f / 64.f);
        float rsB = rsqrtf(fmaxf(qh * (1.f / 64.f) - muB * muB, 0.f) + 1e-5f);

        // fold LN2 and write directly: out = (S - mu*K2)*rs*bs + C0
        {
            const int pw = it * TILE;
            float* oA = out + outbase + (size_t)(2 * t) * (NG * NP) + pw;
            float* oB = out + outbase + (size_t)(2 * t + 1) * (NG * NP) + pw;
            float m1 = rsA * bsa, m2 = rsA * bsb;
            float m3 = rsB * bsa, m4 = rsB * bsb;
            oA[gg]     = fmaf(ddd[0], m1, fmaf(-muA * m1, K2a, C0a));
            oB[gg]     = fmaf(ddd[1], m2, fmaf(-muA * m2, K2b, C0b));
            oA[gg + 8] = fmaf(ddd[2], m3, fmaf(-muB * m3, K2a, C0a));
            oB[gg + 8] = fmaf(ddd[3], m4, fmaf(-muB * m4, K2b, C0b));
        }
    }
}

extern "C" void kernel_launch(void* const* d_in, const int* in_sizes, int n_in,
                              void* d_out, int out_size) {
    // metadata order: grasp_tokens, scene_points, grasp_poses, W1, b1, g1, beta1,
    //                 W2, b2, g2, beta2, W3, b3, bias_scale
    const float* scene  = (const float*)d_in[1];
    const float* poses  = (const float*)d_in[2];
    const float* W1     = (const float*)d_in[3];
    const float* b1     = (const float*)d_in[4];
    const float* g1     = (const float*)d_in[5];
    const float* be1    = (const float*)d_in[6];
    const float* W2     = (const float*)d_in[7];
    const float* b2     = (const float*)d_in[8];
    const float* g2     = (const float*)d_in[9];
    const float* be2    = (const float*)d_in[10];
    const float* W3     = (const float*)d_in[11];
    const float* b3     = (const float*)d_in[12];
    const float* bscale = (const float*)d_in[13];
    float* out = (float*)d_out;

    cudaFuncSetAttribute(gab_kernel, cudaFuncAttributeMaxDynamicSharedMemorySize,
                         (int)sizeof(Smem));
    dim3 grid(NP / PCHUNK, NG / 8, BATCH);
    gab_kernel<<<grid, 256, sizeof(Smem)>>>(scene, poses, W1, b1, g1, be1,
                                            W2, b2, g2, be2, W3, b3, bscale, out);
}